// round 6
// baseline (speedup 1.0000x reference)
#include <cuda_runtime.h>
#include <cuda_bf16.h>
#include <cstdint>
#include <math.h>

#define Bsz 8
#define Sseq 4096
#define Hdim 1024
#define NHEAD 16
#define HDm 64
#define BSROWS (Bsz * Sseq)          // 32768
#define EPS_ATTN 1e-6f
#define EPS_LN 1e-12f

// ---------------- scratch (device globals; no allocation allowed) -----------
__device__ float g_hs[(size_t)BSROWS * Hdim];            // hs (f32)
__device__ __nv_bfloat16 g_qb[(size_t)BSROWS * Hdim];    // q bf16
__device__ __nv_bfloat16 g_kb[(size_t)BSROWS * Hdim];    // k bf16
__device__ __nv_bfloat16 g_vb[(size_t)BSROWS * Hdim];    // v bf16
__device__ float g_kv[Bsz * NHEAD * HDm * HDm];          // kv state [bh][m][d]
__device__ float g_ksum[Bsz * NHEAD * HDm];              // sum_s k  [bh][d]
__device__ __nv_bfloat16 g_xb[(size_t)BSROWS * Hdim];    // x in bf16
__device__ __nv_bfloat16 g_cb[(size_t)BSROWS * Hdim];    // ctx in bf16
__device__ __nv_bfloat16 g_wq[Hdim * Hdim];
__device__ __nv_bfloat16 g_wk[Hdim * Hdim];
__device__ __nv_bfloat16 g_wv[Hdim * Hdim];
__device__ __nv_bfloat16 g_wd[Hdim * Hdim];

// ---------------- PTX helpers -------------------------------------------------
__device__ __forceinline__ uint32_t smem_u32(const void* p) {
    uint32_t a;
    asm("{ .reg .u64 t; cvta.to.shared.u64 t, %1; cvt.u32.u64 %0, t; }" : "=r"(a) : "l"(p));
    return a;
}

__device__ __forceinline__ void ldm_x4(uint32_t& d0, uint32_t& d1, uint32_t& d2,
                                       uint32_t& d3, uint32_t addr) {
    asm volatile("ldmatrix.sync.aligned.m8n8.x4.shared.b16 {%0,%1,%2,%3}, [%4];"
                 : "=r"(d0), "=r"(d1), "=r"(d2), "=r"(d3) : "r"(addr));
}

__device__ __forceinline__ void mma_bf16(float* c, const uint32_t* a, const uint32_t* b) {
    asm volatile(
        "mma.sync.aligned.m16n8k16.row.col.f32.bf16.bf16.f32 "
        "{%0,%1,%2,%3}, {%4,%5,%6,%7}, {%8,%9}, {%0,%1,%2,%3};"
        : "+f"(c[0]), "+f"(c[1]), "+f"(c[2]), "+f"(c[3])
        : "r"(a[0]), "r"(a[1]), "r"(a[2]), "r"(a[3]), "r"(b[0]), "r"(b[1]));
}

__device__ __forceinline__ void cp16(uint32_t dst, const void* src) {
    asm volatile("cp.async.cg.shared.global [%0], [%1], 16;" :: "r"(dst), "l"(src));
}
#define CP_COMMIT() asm volatile("cp.async.commit_group;" ::: "memory")
#define CP_WAIT1()  asm volatile("cp.async.wait_group 1;" ::: "memory")
#define CP_WAIT0()  asm volatile("cp.async.wait_group 0;" ::: "memory")

// ---------------- BF16 tensor-core GEMM: C = A[M,K]bf16 @ W[N,K]^T bf16 ------
// CTA tile 128x256, BK=32, 3-stage cp.async, 8 warps (2x4), warp tile 64x64.
// Rows padded to 40 bf16 (80B) -> conflict-free ldmatrix.
#define BKb 32
#define LDB 40
#define STG 3
#define ATILEB (128 * LDB * 2)       // 10240 B
#define BTILEB (256 * LDB * 2)       // 20480 B
#define STGB   (ATILEB + BTILEB)     // 30720 B
#define GSM_TOT (STG * STGB)         // 92160 B

__global__ __launch_bounds__(256, 1)
void gemm_bf16(const __nv_bfloat16* __restrict__ A, const __nv_bfloat16* __restrict__ W,
               const float* __restrict__ bias, const float* __restrict__ resid,
               float* __restrict__ Cf, __nv_bfloat16* __restrict__ Cb,
               int K, int N, int act)
{
    extern __shared__ char smem[];
    const uint32_t smb = smem_u32(smem);

    const int tid  = threadIdx.x;
    const int lane = tid & 31;
    const int wid  = tid >> 5;
    const int wm   = wid & 1;           // warp row (2)
    const int wn   = wid >> 1;          // warp col (4)
    const int row0 = blockIdx.y * 128;
    const int col0 = blockIdx.x * 256;

    // global->smem mapping: r0 = tid>>2 (0..63), 8-bf16 seg ks
    const int r0 = tid >> 2;
    const int ks = (tid & 3) * 8;

    const __nv_bfloat16* Ap0 = A + (size_t)(row0 + r0) * K + ks;
    const __nv_bfloat16* Ap1 = Ap0 + (size_t)64 * K;
    const __nv_bfloat16* Wp0 = W + (size_t)(col0 + r0) * K + ks;
    const __nv_bfloat16* Wp1 = Wp0 + (size_t)64 * K;
    const __nv_bfloat16* Wp2 = Wp0 + (size_t)128 * K;
    const __nv_bfloat16* Wp3 = Wp0 + (size_t)192 * K;

    const uint32_t st_off = (uint32_t)(r0 * LDB + ks) * 2;

    // ldmatrix lane-invariant offsets (bytes)
    const uint32_t a_lane = ((uint32_t)((wm * 64 + (lane & 15)) * LDB + (lane >> 4) * 8)) * 2;
    const uint32_t b_lane = ((uint32_t)((wn * 64 + ((lane >> 4) << 3) + (lane & 7)) * LDB
                                        + ((lane >> 3) & 1) * 8)) * 2;

    float acc[4][8][4] = {};
    const int nt = K / BKb;             // 32

    // prologue: stages 0,1
    #pragma unroll
    for (int s = 0; s < 2; s++) {
        const int g = s * BKb;
        const uint32_t sb = smb + s * STGB;
        cp16(sb + st_off, Ap0 + g);
        cp16(sb + st_off + 64 * LDB * 2, Ap1 + g);
        cp16(sb + ATILEB + st_off, Wp0 + g);
        cp16(sb + ATILEB + st_off + 64 * LDB * 2, Wp1 + g);
        cp16(sb + ATILEB + st_off + 128 * LDB * 2, Wp2 + g);
        cp16(sb + ATILEB + st_off + 192 * LDB * 2, Wp3 + g);
        CP_COMMIT();
    }

    int stage = 0;
    for (int kt = 0; kt < nt; kt++) {
        if (kt == nt - 1) CP_WAIT0(); else CP_WAIT1();
        __syncthreads();

        if (kt + 2 < nt) {
            const int g = (kt + 2) * BKb;
            const int s2 = (stage + 2 >= STG) ? (stage + 2 - STG) : (stage + 2);
            const uint32_t sb = smb + s2 * STGB;
            cp16(sb + st_off, Ap0 + g);
            cp16(sb + st_off + 64 * LDB * 2, Ap1 + g);
            cp16(sb + ATILEB + st_off, Wp0 + g);
            cp16(sb + ATILEB + st_off + 64 * LDB * 2, Wp1 + g);
            cp16(sb + ATILEB + st_off + 128 * LDB * 2, Wp2 + g);
            cp16(sb + ATILEB + st_off + 192 * LDB * 2, Wp3 + g);
            CP_COMMIT();
        }

        const uint32_t ab = smb + stage * STGB + a_lane;
        const uint32_t bb = smb + stage * STGB + ATILEB + b_lane;

        #pragma unroll
        for (int kk = 0; kk < BKb; kk += 16) {
            uint32_t af[4][4], bf[8][2];
            #pragma unroll
            for (int mf = 0; mf < 4; mf++)
                ldm_x4(af[mf][0], af[mf][1], af[mf][2], af[mf][3],
                       ab + (uint32_t)(mf * 16 * LDB + kk) * 2);
            #pragma unroll
            for (int np = 0; np < 4; np++)
                ldm_x4(bf[np * 2][0], bf[np * 2][1], bf[np * 2 + 1][0], bf[np * 2 + 1][1],
                       bb + (uint32_t)(np * 16 * LDB + kk) * 2);
            #pragma unroll
            for (int mf = 0; mf < 4; mf++)
                #pragma unroll
                for (int nf = 0; nf < 8; nf++)
                    mma_bf16(acc[mf][nf], af[mf], bf[nf]);
        }

        stage = (stage + 1 == STG) ? 0 : (stage + 1);
    }

    // epilogue: bias (+resid) (+elu+1); output f32 or bf16
    #pragma unroll
    for (int mf = 0; mf < 4; mf++) {
        #pragma unroll
        for (int nf = 0; nf < 8; nf++) {
            const int r   = row0 + wm * 64 + mf * 16 + (lane >> 2);
            const int cgl = col0 + wn * 64 + nf * 8 + 2 * (lane & 3);
            const float b0 = bias[cgl], b1 = bias[cgl + 1];
            #pragma unroll
            for (int half = 0; half < 2; half++) {
                const int rr = r + half * 8;
                float v0 = acc[mf][nf][half * 2 + 0] + b0;
                float v1 = acc[mf][nf][half * 2 + 1] + b1;
                if (resid) {
                    const float* rp = resid + (size_t)rr * N + cgl;
                    v0 += rp[0];
                    v1 += rp[1];
                }
                if (act) {
                    v0 = (v0 > 0.f) ? (v0 + 1.f) : expf(v0);
                    v1 = (v1 > 0.f) ? (v1 + 1.f) : expf(v1);
                }
                if (Cb) {
                    *(__nv_bfloat162*)(Cb + (size_t)rr * N + cgl) =
                        __floats2bfloat162_rn(v0, v1);
                } else {
                    *(float2*)(Cf + (size_t)rr * N + cgl) = make_float2(v0, v1);
                }
            }
        }
    }
}

// ---------------- f32 -> bf16 conversion -------------------------------------
__global__ void __launch_bounds__(256)
conv_bf16(const float* __restrict__ in, __nv_bfloat16* __restrict__ out, int n4)
{
    const int i = blockIdx.x * blockDim.x + threadIdx.x;
    if (i < n4) {
        float4 v = ((const float4*)in)[i];
        __nv_bfloat162 lo = __floats2bfloat162_rn(v.x, v.y);
        __nv_bfloat162 hi = __floats2bfloat162_rn(v.z, v.w);
        uint2 u;
        u.x = *reinterpret_cast<uint32_t*>(&lo);
        u.y = *reinterpret_cast<uint32_t*>(&hi);
        ((uint2*)out)[i] = u;
    }
}

// ---------------- kv state + ksum:  kv[bh][m][d] = sum_s v[s][m] * k[s][d]
__global__ __launch_bounds__(256)
void kv_accum(const __nv_bfloat16* __restrict__ k, const __nv_bfloat16* __restrict__ v,
              float* __restrict__ kv, float* __restrict__ ksum)
{
    const int bh = blockIdx.x;
    const int b  = bh / NHEAD, h = bh % NHEAD;
    const int s0 = blockIdx.y * (Sseq / 8);

    __shared__ float ks[4][HDm];
    __shared__ float vs[4][HDm];

    const int tid = threadIdx.x;
    const int tx = tid & 15, ty = tid >> 4;
    const int d0 = tx * 4, m0 = ty * 4;
    const int tt = tid >> 6;
    const int cc = tid & 63;

    float acc[4][4];
    #pragma unroll
    for (int m = 0; m < 4; m++)
        #pragma unroll
        for (int d = 0; d < 4; d++) acc[m][d] = 0.f;
    float kloc = 0.f;

    for (int s = s0; s < s0 + Sseq / 8; s += 4) {
        __syncthreads();
        const size_t base = ((size_t)(b * Sseq + s + tt)) * Hdim + h * HDm + cc;
        ks[tt][cc] = __bfloat162float(k[base]);
        vs[tt][cc] = __bfloat162float(v[base]);
        __syncthreads();

        #pragma unroll
        for (int t = 0; t < 4; t++) {
            float kk4[4] = {ks[t][d0], ks[t][d0 + 1], ks[t][d0 + 2], ks[t][d0 + 3]};
            float vv4[4] = {vs[t][m0], vs[t][m0 + 1], vs[t][m0 + 2], vs[t][m0 + 3]};
            #pragma unroll
            for (int m = 0; m < 4; m++)
                #pragma unroll
                for (int d = 0; d < 4; d++)
                    acc[m][d] = fmaf(vv4[m], kk4[d], acc[m][d]);
        }
        if (tid < HDm)
            kloc += ks[0][tid] + ks[1][tid] + ks[2][tid] + ks[3][tid];
    }

    float* kvp = kv + (size_t)bh * HDm * HDm;
    #pragma unroll
    for (int m = 0; m < 4; m++)
        #pragma unroll
        for (int d = 0; d < 4; d++)
            atomicAdd(&kvp[(m0 + m) * HDm + (d0 + d)], acc[m][d]);
    if (tid < HDm) atomicAdd(&ksum[bh * HDm + tid], kloc);
}

// ---------------- ctx[s][m] = (q[s].kv[m,:]) * z[s];  z = 1/(q.(ksum+eps))
__global__ __launch_bounds__(256)
void ctx_kernel(const __nv_bfloat16* __restrict__ q, const float* __restrict__ kv,
                const float* __restrict__ ksum, __nv_bfloat16* __restrict__ ctx)
{
    const int bh = blockIdx.x;
    const int b = bh / NHEAD, h = bh % NHEAD;
    const int s0 = blockIdx.y * 128;

    __shared__ float kvT[HDm][HDm];
    __shared__ float kse[HDm];
    __shared__ float qsh[4][HDm];
    __shared__ float zp[4][2];

    const int tid = threadIdx.x;
    const float* kvp = kv + (size_t)bh * HDm * HDm;
    for (int i = tid; i < HDm * HDm; i += 256)
        kvT[i & 63][i >> 6] = kvp[i];
    if (tid < HDm) kse[tid] = ksum[bh * HDm + tid] + EPS_ATTN;
    __syncthreads();

    const int ty   = tid >> 6;      // token within group of 4
    const int m    = tid & 63;
    const int lane = tid & 31;
    const int half = (m >> 5);      // 0: m<32, 1: m>=32

    for (int g = 0; g < 32; g++) {
        const int s = s0 + g * 4 + ty;
        const size_t base = ((size_t)(b * Sseq + s)) * Hdim + h * HDm;
        const float qv = __bfloat162float(q[base + m]);
        qsh[ty][m] = qv;

        // partial normalizer: this thread's d == m
        float p = qv * kse[m];
        #pragma unroll
        for (int o = 16; o > 0; o >>= 1)
            p += __shfl_xor_sync(0xFFFFFFFFu, p, o);
        if (lane == 0) zp[ty][half] = p;
        __syncthreads();

        const float dot = zp[ty][0] + zp[ty][1];
        float acc = 0.f;
        #pragma unroll 8
        for (int d = 0; d < HDm; d++)
            acc = fmaf(qsh[ty][d], kvT[d][m], acc);
        ctx[base + m] = __float2bfloat16(acc / dot);
        __syncthreads();
    }
}

// ---------------- LayerNorm over rows of 1024
__global__ __launch_bounds__(256)
void ln_kernel(const float* __restrict__ hs, const float* __restrict__ gamma,
               const float* __restrict__ beta, float* __restrict__ out)
{
    const int row = blockIdx.x;
    const int tid = threadIdx.x;
    const float4 v = ((const float4*)(hs + (size_t)row * Hdim))[tid];

    float s  = v.x + v.y + v.z + v.w;
    float sq = v.x * v.x + v.y * v.y + v.z * v.z + v.w * v.w;
    #pragma unroll
    for (int o = 16; o > 0; o >>= 1) {
        s  += __shfl_xor_sync(0xFFFFFFFFu, s, o);
        sq += __shfl_xor_sync(0xFFFFFFFFu, sq, o);
    }
    __shared__ float rs[8], rq[8];
    const int wid = tid >> 5, lane = tid & 31;
    if (lane == 0) { rs[wid] = s; rq[wid] = sq; }
    __syncthreads();
    float sum = 0.f, sumq = 0.f;
    #pragma unroll
    for (int i = 0; i < 8; i++) { sum += rs[i]; sumq += rq[i]; }

    const float mu   = sum * (1.f / Hdim);
    const float var  = sumq * (1.f / Hdim) - mu * mu;
    const float rstd = rsqrtf(var + EPS_LN);

    const float4 g4 = ((const float4*)gamma)[tid];
    const float4 b4 = ((const float4*)beta)[tid];
    float4 o;
    o.x = (v.x - mu) * rstd * g4.x + b4.x;
    o.y = (v.y - mu) * rstd * g4.y + b4.y;
    o.z = (v.z - mu) * rstd * g4.z + b4.z;
    o.w = (v.w - mu) * rstd * g4.w + b4.w;
    ((float4*)(out + (size_t)row * Hdim))[tid] = o;
}

__global__ void zero_kernel(float* p, int n)
{
    const int i = blockIdx.x * blockDim.x + threadIdx.x;
    if (i < n) p[i] = 0.f;
}

// ---------------- launch ----------------------------------------------------
extern "C" void kernel_launch(void* const* d_in, const int* in_sizes, int n_in,
                              void* d_out, int out_size)
{
    const float* x     = (const float*)d_in[0];
    const float* Wq    = (const float*)d_in[2];
    const float* bq    = (const float*)d_in[3];
    const float* Wk    = (const float*)d_in[4];
    const float* bk    = (const float*)d_in[5];
    const float* Wv    = (const float*)d_in[6];
    const float* bv    = (const float*)d_in[7];
    const float* Wd    = (const float*)d_in[8];
    const float* bd    = (const float*)d_in[9];
    const float* gamma = (const float*)d_in[10];
    const float* beta  = (const float*)d_in[11];
    float* out = (float*)d_out;

    float *hs, *kv, *ksum;
    __nv_bfloat16 *qb, *kb, *vb, *xb, *cb, *wqb, *wkb, *wvb, *wdb;
    cudaGetSymbolAddress((void**)&hs,   g_hs);
    cudaGetSymbolAddress((void**)&qb,   g_qb);
    cudaGetSymbolAddress((void**)&kb,   g_kb);
    cudaGetSymbolAddress((void**)&vb,   g_vb);
    cudaGetSymbolAddress((void**)&kv,   g_kv);
    cudaGetSymbolAddress((void**)&ksum, g_ksum);
    cudaGetSymbolAddress((void**)&xb,   g_xb);
    cudaGetSymbolAddress((void**)&cb,   g_cb);
    cudaGetSymbolAddress((void**)&wqb,  g_wq);
    cudaGetSymbolAddress((void**)&wkb,  g_wk);
    cudaGetSymbolAddress((void**)&wvb,  g_wv);
    cudaGetSymbolAddress((void**)&wdb,  g_wd);

    cudaFuncSetAttribute(gemm_bf16, cudaFuncAttributeMaxDynamicSharedMemorySize, GSM_TOT);

    // convert inputs to bf16
    const int xn4 = (int)((size_t)BSROWS * Hdim / 4);
    const int wn4 = Hdim * Hdim / 4;
    conv_bf16<<<xn4 / 256, 256>>>(x,  xb,  xn4);
    conv_bf16<<<wn4 / 256, 256>>>(Wq, wqb, wn4);
    conv_bf16<<<wn4 / 256, 256>>>(Wk, wkb, wn4);
    conv_bf16<<<wn4 / 256, 256>>>(Wv, wvb, wn4);
    conv_bf16<<<wn4 / 256, 256>>>(Wd, wdb, wn4);

    const dim3 ggrid(Hdim / 256, BSROWS / 128);   // (4, 256)

    // QKV projections (+ elu+1 on q,k) — bf16 outputs
    gemm_bf16<<<ggrid, 256, GSM_TOT>>>(xb, wqb, bq, nullptr, nullptr, qb, Hdim, Hdim, 1);
    gemm_bf16<<<ggrid, 256, GSM_TOT>>>(xb, wkb, bk, nullptr, nullptr, kb, Hdim, Hdim, 1);
    gemm_bf16<<<ggrid, 256, GSM_TOT>>>(xb, wvb, bv, nullptr, nullptr, vb, Hdim, Hdim, 0);

    // zero kv state (graph replays must be deterministic)
    const int kvn = Bsz * NHEAD * HDm * HDm;
    const int ksn = Bsz * NHEAD * HDm;
    zero_kernel<<<(kvn + 255) / 256, 256>>>(kv, kvn);
    zero_kernel<<<(ksn + 255) / 256, 256>>>(ksum, ksn);

    // kv state + ksum
    kv_accum<<<dim3(Bsz * NHEAD, 8), 256>>>(kb, vb, kv, ksum);

    // ctx -> bf16
    ctx_kernel<<<dim3(Bsz * NHEAD, Sseq / 128), 256>>>(qb, kv, ksum, cb);

    // output projection + bias + residual -> hs (f32)
    gemm_bf16<<<ggrid, 256, GSM_TOT>>>(cb, wdb, bd, x, hs, nullptr, Hdim, Hdim, 0);

    // LayerNorm
    ln_kernel<<<BSROWS, 256>>>(hs, gamma, beta, out);
}

// round 7
// speedup vs baseline: 1.1589x; 1.1589x over previous
#include <cuda_runtime.h>
#include <cuda_bf16.h>
#include <cstdint>
#include <math.h>

#define Bsz 8
#define Sseq 4096
#define Hdim 1024
#define NHEAD 16
#define HDm 64
#define BSROWS (Bsz * Sseq)          // 32768
#define EPS_ATTN 1e-6f
#define EPS_LN 1e-12f

// ---------------- scratch (device globals; no allocation allowed) -----------
__device__ float g_hs[(size_t)BSROWS * Hdim];            // hs (f32)
__device__ __nv_bfloat16 g_qb[(size_t)BSROWS * Hdim];    // q bf16
__device__ __nv_bfloat16 g_kb[(size_t)BSROWS * Hdim];    // k bf16
__device__ __nv_bfloat16 g_vb[(size_t)BSROWS * Hdim];    // v bf16
__device__ float g_kv[Bsz * NHEAD * HDm * HDm];          // kv state [bh][m][d]
__device__ float g_ksum[Bsz * NHEAD * HDm];              // sum_s k  [bh][d]
__device__ __nv_bfloat16 g_xb[(size_t)BSROWS * Hdim];    // x in bf16
__device__ __nv_bfloat16 g_cb[(size_t)BSROWS * Hdim];    // ctx in bf16
__device__ __nv_bfloat16 g_wqkv[3 * Hdim * Hdim];        // Wq|Wk|Wv bf16
__device__ __nv_bfloat16 g_wd[Hdim * Hdim];

// ---------------- PTX helpers -------------------------------------------------
__device__ __forceinline__ uint32_t smem_u32(const void* p) {
    uint32_t a;
    asm("{ .reg .u64 t; cvta.to.shared.u64 t, %1; cvt.u32.u64 %0, t; }" : "=r"(a) : "l"(p));
    return a;
}

__device__ __forceinline__ void ldm_x4(uint32_t& d0, uint32_t& d1, uint32_t& d2,
                                       uint32_t& d3, uint32_t addr) {
    asm volatile("ldmatrix.sync.aligned.m8n8.x4.shared.b16 {%0,%1,%2,%3}, [%4];"
                 : "=r"(d0), "=r"(d1), "=r"(d2), "=r"(d3) : "r"(addr));
}

__device__ __forceinline__ void mma_bf16(float* c, const uint32_t* a, const uint32_t* b) {
    asm volatile(
        "mma.sync.aligned.m16n8k16.row.col.f32.bf16.bf16.f32 "
        "{%0,%1,%2,%3}, {%4,%5,%6,%7}, {%8,%9}, {%0,%1,%2,%3};"
        : "+f"(c[0]), "+f"(c[1]), "+f"(c[2]), "+f"(c[3])
        : "r"(a[0]), "r"(a[1]), "r"(a[2]), "r"(a[3]), "r"(b[0]), "r"(b[1]));
}

__device__ __forceinline__ void cp16(uint32_t dst, const void* src) {
    asm volatile("cp.async.cg.shared.global [%0], [%1], 16;" :: "r"(dst), "l"(src));
}
#define CP_COMMIT() asm volatile("cp.async.commit_group;" ::: "memory")
#define CP_WAIT0()  asm volatile("cp.async.wait_group 0;" ::: "memory")

// ---------------- BF16 tensor-core GEMM --------------------------------------
// CTA tile 128x128 over W rows [col0, col0+128), BK=64, 2-stage cp.async,
// 8 warps (2x4), warp tile 64x32. Rows padded to 72 bf16 (144B = 9*16B,
// odd multiple of 16 -> conflict-free ldmatrix + stores).
// QKV-fused mode: W is [3072,1024]; per-CTA sel=col0>>10 picks bias/out/act.
#define BKb 64
#define LDB 72
#define TILEB (128 * LDB * 2)        // 18432 B
#define STGB  (2 * TILEB)            // 36864 B
#define GSM_TOT (2 * STGB)           // 73728 B

__global__ __launch_bounds__(256, 2)
void gemm_bf16(const __nv_bfloat16* __restrict__ A, const __nv_bfloat16* __restrict__ W,
               const float* __restrict__ b0, const float* __restrict__ b1,
               const float* __restrict__ b2, const float* __restrict__ resid,
               float* __restrict__ Cf,
               __nv_bfloat16* __restrict__ o0, __nv_bfloat16* __restrict__ o1,
               __nv_bfloat16* __restrict__ o2,
               int K, int actQK)
{
    extern __shared__ char smem[];
    const uint32_t smb = smem_u32(smem);

    const int tid  = threadIdx.x;
    const int lane = tid & 31;
    const int wid  = tid >> 5;
    const int wm   = wid & 1;           // warp row (2)
    const int wn   = wid >> 1;          // warp col (4)
    const int row0 = blockIdx.y * 128;
    const int col0 = blockIdx.x * 128;  // global W-row offset (may exceed 1024)

    // per-CTA output select (uniform)
    const int sel = col0 >> 10;
    const int lc0 = col0 & 1023;
    const float* bias = (sel == 0) ? b0 : ((sel == 1) ? b1 : b2);
    __nv_bfloat16* Cb = (sel == 0) ? o0 : ((sel == 1) ? o1 : o2);
    const int act = actQK && (sel < 2);

    // global->smem: each thread covers 4 segs per 128x64 tile
    // seg = tid + 256*j : r = seg>>3 (0..127), ksg = seg&7 (16B seg within 64 bf16)
    const int rA = tid >> 3;
    const int kg = (tid & 7) * 8;       // bf16 offset of this thread's seg

    const __nv_bfloat16* Ap0 = A + (size_t)(row0 + rA) * K + kg;
    const __nv_bfloat16* Ap1 = Ap0 + (size_t)32 * K;
    const __nv_bfloat16* Ap2 = Ap0 + (size_t)64 * K;
    const __nv_bfloat16* Ap3 = Ap0 + (size_t)96 * K;
    const __nv_bfloat16* Wp0 = W + (size_t)(col0 + rA) * K + kg;
    const __nv_bfloat16* Wp1 = Wp0 + (size_t)32 * K;
    const __nv_bfloat16* Wp2 = Wp0 + (size_t)64 * K;
    const __nv_bfloat16* Wp3 = Wp0 + (size_t)96 * K;

    const uint32_t st_off = (uint32_t)(rA * LDB + kg) * 2;
    const uint32_t rstep  = (uint32_t)(32 * LDB) * 2;

    // ldmatrix lane-invariant offsets (bytes)
    const uint32_t a_lane = ((uint32_t)((wm * 64 + (lane & 15)) * LDB + (lane >> 4) * 8)) * 2;
    const uint32_t b_lane = ((uint32_t)((wn * 32 + ((lane >> 4) << 3) + (lane & 7)) * LDB
                                        + ((lane >> 3) & 1) * 8)) * 2;

    float acc[4][4][4] = {};
    const int nt = K / BKb;             // 16

    // prologue: stage 0
    {
        const uint32_t sb = smb;
        cp16(sb + st_off,             Ap0);
        cp16(sb + st_off + rstep,     Ap1);
        cp16(sb + st_off + 2 * rstep, Ap2);
        cp16(sb + st_off + 3 * rstep, Ap3);
        cp16(sb + TILEB + st_off,             Wp0);
        cp16(sb + TILEB + st_off + rstep,     Wp1);
        cp16(sb + TILEB + st_off + 2 * rstep, Wp2);
        cp16(sb + TILEB + st_off + 3 * rstep, Wp3);
        CP_COMMIT();
    }

    for (int kt = 0; kt < nt; kt++) {
        CP_WAIT0();
        __syncthreads();

        if (kt + 1 < nt) {
            const int g = (kt + 1) * BKb;
            const uint32_t sb = smb + ((kt + 1) & 1) * STGB;
            cp16(sb + st_off,             Ap0 + g);
            cp16(sb + st_off + rstep,     Ap1 + g);
            cp16(sb + st_off + 2 * rstep, Ap2 + g);
            cp16(sb + st_off + 3 * rstep, Ap3 + g);
            cp16(sb + TILEB + st_off,             Wp0 + g);
            cp16(sb + TILEB + st_off + rstep,     Wp1 + g);
            cp16(sb + TILEB + st_off + 2 * rstep, Wp2 + g);
            cp16(sb + TILEB + st_off + 3 * rstep, Wp3 + g);
            CP_COMMIT();
        }

        const uint32_t ab = smb + (kt & 1) * STGB + a_lane;
        const uint32_t bb = smb + (kt & 1) * STGB + TILEB + b_lane;

        #pragma unroll
        for (int kk = 0; kk < BKb; kk += 16) {
            uint32_t af[4][4], bf[4][2];
            #pragma unroll
            for (int mf = 0; mf < 4; mf++)
                ldm_x4(af[mf][0], af[mf][1], af[mf][2], af[mf][3],
                       ab + (uint32_t)(mf * 16 * LDB + kk) * 2);
            #pragma unroll
            for (int np = 0; np < 2; np++)
                ldm_x4(bf[np * 2][0], bf[np * 2][1], bf[np * 2 + 1][0], bf[np * 2 + 1][1],
                       bb + (uint32_t)(np * 16 * LDB + kk) * 2);
            #pragma unroll
            for (int mf = 0; mf < 4; mf++)
                #pragma unroll
                for (int nf = 0; nf < 4; nf++)
                    mma_bf16(acc[mf][nf], af[mf], bf[nf]);
        }
    }

    // epilogue: bias (+resid) (+elu+1); output f32 or bf16
    #pragma unroll
    for (int mf = 0; mf < 4; mf++) {
        #pragma unroll
        for (int nf = 0; nf < 4; nf++) {
            const int r   = row0 + wm * 64 + mf * 16 + (lane >> 2);
            const int cgl = lc0 + wn * 32 + nf * 8 + 2 * (lane & 3);
            const float bb0 = bias[cgl], bb1 = bias[cgl + 1];
            #pragma unroll
            for (int half = 0; half < 2; half++) {
                const int rr = r + half * 8;
                float v0 = acc[mf][nf][half * 2 + 0] + bb0;
                float v1 = acc[mf][nf][half * 2 + 1] + bb1;
                if (resid) {
                    const float* rp = resid + (size_t)rr * Hdim + cgl;
                    v0 += rp[0];
                    v1 += rp[1];
                }
                if (act) {
                    v0 = (v0 > 0.f) ? (v0 + 1.f) : expf(v0);
                    v1 = (v1 > 0.f) ? (v1 + 1.f) : expf(v1);
                }
                if (Cf) {
                    *(float2*)(Cf + (size_t)rr * Hdim + cgl) = make_float2(v0, v1);
                } else {
                    *(__nv_bfloat162*)(Cb + (size_t)rr * Hdim + cgl) =
                        __floats2bfloat162_rn(v0, v1);
                }
            }
        }
    }
}

// ---------------- f32 -> bf16 conversion -------------------------------------
__global__ void __launch_bounds__(256)
conv_bf16(const float* __restrict__ in, __nv_bfloat16* __restrict__ out, int n4)
{
    const int i = blockIdx.x * blockDim.x + threadIdx.x;
    if (i < n4) {
        float4 v = ((const float4*)in)[i];
        __nv_bfloat162 lo = __floats2bfloat162_rn(v.x, v.y);
        __nv_bfloat162 hi = __floats2bfloat162_rn(v.z, v.w);
        uint2 u;
        u.x = *reinterpret_cast<uint32_t*>(&lo);
        u.y = *reinterpret_cast<uint32_t*>(&hi);
        ((uint2*)out)[i] = u;
    }
}

// ---------------- kv state + ksum:  kv[bh][m][d] = sum_s v[s][m] * k[s][d]
__global__ __launch_bounds__(256)
void kv_accum(const __nv_bfloat16* __restrict__ k, const __nv_bfloat16* __restrict__ v,
              float* __restrict__ kv, float* __restrict__ ksum)
{
    const int bh = blockIdx.x;
    const int b  = bh / NHEAD, h = bh % NHEAD;
    const int s0 = blockIdx.y * (Sseq / 8);

    __shared__ float ks[4][HDm];
    __shared__ float vs[4][HDm];

    const int tid = threadIdx.x;
    const int tx = tid & 15, ty = tid >> 4;
    const int d0 = tx * 4, m0 = ty * 4;
    const int tt = tid >> 6;
    const int cc = tid & 63;

    float acc[4][4];
    #pragma unroll
    for (int m = 0; m < 4; m++)
        #pragma unroll
        for (int d = 0; d < 4; d++) acc[m][d] = 0.f;
    float kloc = 0.f;

    for (int s = s0; s < s0 + Sseq / 8; s += 4) {
        __syncthreads();
        const size_t base = ((size_t)(b * Sseq + s + tt)) * Hdim + h * HDm + cc;
        ks[tt][cc] = __bfloat162float(k[base]);
        vs[tt][cc] = __bfloat162float(v[base]);
        __syncthreads();

        #pragma unroll
        for (int t = 0; t < 4; t++) {
            float kk4[4] = {ks[t][d0], ks[t][d0 + 1], ks[t][d0 + 2], ks[t][d0 + 3]};
            float vv4[4] = {vs[t][m0], vs[t][m0 + 1], vs[t][m0 + 2], vs[t][m0 + 3]};
            #pragma unroll
            for (int m = 0; m < 4; m++)
                #pragma unroll
                for (int d = 0; d < 4; d++)
                    acc[m][d] = fmaf(vv4[m], kk4[d], acc[m][d]);
        }
        if (tid < HDm)
            kloc += ks[0][tid] + ks[1][tid] + ks[2][tid] + ks[3][tid];
    }

    float* kvp = kv + (size_t)bh * HDm * HDm;
    #pragma unroll
    for (int m = 0; m < 4; m++)
        #pragma unroll
        for (int d = 0; d < 4; d++)
            atomicAdd(&kvp[(m0 + m) * HDm + (d0 + d)], acc[m][d]);
    if (tid < HDm) atomicAdd(&ksum[bh * HDm + tid], kloc);
}

// ---------------- ctx[s][m] = (q[s].kv[m,:]) / (q[s].(ksum+eps)) -> bf16
__global__ __launch_bounds__(256)
void ctx_kernel(const __nv_bfloat16* __restrict__ q, const float* __restrict__ kv,
                const float* __restrict__ ksum, __nv_bfloat16* __restrict__ ctx)
{
    const int bh = blockIdx.x;
    const int b = bh / NHEAD, h = bh % NHEAD;
    const int s0 = blockIdx.y * 128;

    __shared__ float kvT[HDm][HDm];
    __shared__ float kse[HDm];
    __shared__ float qsh[4][HDm];
    __shared__ float zp[4][2];

    const int tid = threadIdx.x;
    const float* kvp = kv + (size_t)bh * HDm * HDm;
    for (int i = tid; i < HDm * HDm; i += 256)
        kvT[i & 63][i >> 6] = kvp[i];
    if (tid < HDm) kse[tid] = ksum[bh * HDm + tid] + EPS_ATTN;
    __syncthreads();

    const int ty   = tid >> 6;
    const int m    = tid & 63;
    const int lane = tid & 31;
    const int half = (m >> 5);

    for (int g = 0; g < 32; g++) {
        const int s = s0 + g * 4 + ty;
        const size_t base = ((size_t)(b * Sseq + s)) * Hdim + h * HDm;
        const float qv = __bfloat162float(q[base + m]);
        qsh[ty][m] = qv;

        float p = qv * kse[m];
        #pragma unroll
        for (int o = 16; o > 0; o >>= 1)
            p += __shfl_xor_sync(0xFFFFFFFFu, p, o);
        if (lane == 0) zp[ty][half] = p;
        __syncthreads();

        const float dot = zp[ty][0] + zp[ty][1];
        float acc = 0.f;
        #pragma unroll 8
        for (int d = 0; d < HDm; d++)
            acc = fmaf(qsh[ty][d], kvT[d][m], acc);
        ctx[base + m] = __float2bfloat16(acc / dot);
        __syncthreads();
    }
}

// ---------------- LayerNorm over rows of 1024
__global__ __launch_bounds__(256)
void ln_kernel(const float* __restrict__ hs, const float* __restrict__ gamma,
               const float* __restrict__ beta, float* __restrict__ out)
{
    const int row = blockIdx.x;
    const int tid = threadIdx.x;
    const float4 v = ((const float4*)(hs + (size_t)row * Hdim))[tid];

    float s  = v.x + v.y + v.z + v.w;
    float sq = v.x * v.x + v.y * v.y + v.z * v.z + v.w * v.w;
    #pragma unroll
    for (int o = 16; o > 0; o >>= 1) {
        s  += __shfl_xor_sync(0xFFFFFFFFu, s, o);
        sq += __shfl_xor_sync(0xFFFFFFFFu, sq, o);
    }
    __shared__ float rs[8], rq[8];
    const int wid = tid >> 5, lane = tid & 31;
    if (lane == 0) { rs[wid] = s; rq[wid] = sq; }
    __syncthreads();
    float sum = 0.f, sumq = 0.f;
    #pragma unroll
    for (int i = 0; i < 8; i++) { sum += rs[i]; sumq += rq[i]; }

    const float mu   = sum * (1.f / Hdim);
    const float var  = sumq * (1.f / Hdim) - mu * mu;
    const float rstd = rsqrtf(var + EPS_LN);

    const float4 g4 = ((const float4*)gamma)[tid];
    const float4 b4 = ((const float4*)beta)[tid];
    float4 o;
    o.x = (v.x - mu) * rstd * g4.x + b4.x;
    o.y = (v.y - mu) * rstd * g4.y + b4.y;
    o.z = (v.z - mu) * rstd * g4.z + b4.z;
    o.w = (v.w - mu) * rstd * g4.w + b4.w;
    ((float4*)(out + (size_t)row * Hdim))[tid] = o;
}

__global__ void zero_kernel(float* p, int n)
{
    const int i = blockIdx.x * blockDim.x + threadIdx.x;
    if (i < n) p[i] = 0.f;
}

// ---------------- launch ----------------------------------------------------
extern "C" void kernel_launch(void* const* d_in, const int* in_sizes, int n_in,
                              void* d_out, int out_size)
{
    const float* x     = (const float*)d_in[0];
    const float* Wq    = (const float*)d_in[2];
    const float* bq    = (const float*)d_in[3];
    const float* Wk    = (const float*)d_in[4];
    const float* bk    = (const float*)d_in[5];
    const float* Wv    = (const float*)d_in[6];
    const float* bv    = (const float*)d_in[7];
    const float* Wd    = (const float*)d_in[8];
    const float* bd    = (const float*)d_in[9];
    const float* gamma = (const float*)d_in[10];
    const float* beta  = (const float*)d_in[11];
    float* out = (float*)d_out;

    float *hs, *kv, *ksum;
    __nv_bfloat16 *qb, *kb, *vb, *xb, *cb, *wqkv, *wdb;
    cudaGetSymbolAddress((void**)&hs,   g_hs);
    cudaGetSymbolAddress((void**)&qb,   g_qb);
    cudaGetSymbolAddress((void**)&kb,   g_kb);
    cudaGetSymbolAddress((void**)&vb,   g_vb);
    cudaGetSymbolAddress((void**)&kv,   g_kv);
    cudaGetSymbolAddress((void**)&ksum, g_ksum);
    cudaGetSymbolAddress((void**)&xb,   g_xb);
    cudaGetSymbolAddress((void**)&cb,   g_cb);
    cudaGetSymbolAddress((void**)&wqkv, g_wqkv);
    cudaGetSymbolAddress((void**)&wdb,  g_wd);

    cudaFuncSetAttribute(gemm_bf16, cudaFuncAttributeMaxDynamicSharedMemorySize, GSM_TOT);

    const int xn4 = (int)((size_t)BSROWS * Hdim / 4);
    const int wn4 = Hdim * Hdim / 4;

    // idx0-3: convert x + QKV weights (into concatenated buffer)
    conv_bf16<<<xn4 / 256, 256>>>(x,  xb, xn4);
    conv_bf16<<<wn4 / 256, 256>>>(Wq, wqkv,                 wn4);
    conv_bf16<<<wn4 / 256, 256>>>(Wk, wqkv + Hdim * Hdim,   wn4);
    conv_bf16<<<wn4 / 256, 256>>>(Wv, wqkv + 2 * Hdim * Hdim, wn4);

    // idx4: fused QKV GEMM (+ elu+1 on q,k), bf16 outputs
    gemm_bf16<<<dim3(3 * Hdim / 128, BSROWS / 128), 256, GSM_TOT>>>(
        xb, wqkv, bq, bk, bv, nullptr, nullptr, qb, kb, vb, Hdim, 1);

    // zero kv state (graph replays must be deterministic)
    const int kvn = Bsz * NHEAD * HDm * HDm;
    const int ksn = Bsz * NHEAD * HDm;
    zero_kernel<<<(kvn + 255) / 256, 256>>>(kv, kvn);
    zero_kernel<<<(ksn + 255) / 256, 256>>>(ksum, ksn);

    // kv state + ksum
    kv_accum<<<dim3(Bsz * NHEAD, 8), 256>>>(kb, vb, kv, ksum);

    // ctx -> bf16
    ctx_kernel<<<dim3(Bsz * NHEAD, Sseq / 128), 256>>>(qb, kv, ksum, cb);

    // Wd conversion (deferred: only needed now)
    conv_bf16<<<wn4 / 256, 256>>>(Wd, wdb, wn4);

    // output projection + bias + residual -> hs (f32)
    gemm_bf16<<<dim3(Hdim / 128, BSROWS / 128), 256, GSM_TOT>>>(
        cb, wdb, bd, bd, bd, x, hs, nullptr, nullptr, nullptr, Hdim, 0);

    // LayerNorm
    ln_kernel<<<BSROWS, 256>>>(hs, gamma, beta, out);
}

// round 8
// speedup vs baseline: 1.6980x; 1.4652x over previous
#include <cuda_runtime.h>
#include <cuda_bf16.h>
#include <cstdint>
#include <math.h>

#define Bsz 8
#define Sseq 4096
#define Hdim 1024
#define NHEAD 16
#define HDm 64
#define BSROWS (Bsz * Sseq)          // 32768
#define EPS_ATTN 1e-6f
#define EPS_LN 1e-12f

// ---------------- scratch (device globals; no allocation allowed) -----------
__device__ float g_hs[(size_t)BSROWS * Hdim];            // hs (f32)
__device__ __nv_bfloat16 g_qb[(size_t)BSROWS * Hdim];    // q bf16
__device__ __nv_bfloat16 g_kb[(size_t)BSROWS * Hdim];    // k bf16
__device__ __nv_bfloat16 g_vb[(size_t)BSROWS * Hdim];    // v bf16
__device__ float g_kv[Bsz * NHEAD * HDm * HDm];          // kv state [bh][m][d]
__device__ float g_ksum[Bsz * NHEAD * HDm];              // sum_s k  [bh][d]
__device__ __nv_bfloat16 g_xb[(size_t)BSROWS * Hdim];    // x in bf16
__device__ __nv_bfloat16 g_cb[(size_t)BSROWS * Hdim];    // ctx in bf16
__device__ __nv_bfloat16 g_wqkv[3 * Hdim * Hdim];        // Wq|Wk|Wv bf16
__device__ __nv_bfloat16 g_wd[Hdim * Hdim];

// ---------------- PTX helpers -------------------------------------------------
__device__ __forceinline__ uint32_t smem_u32(const void* p) {
    uint32_t a;
    asm("{ .reg .u64 t; cvta.to.shared.u64 t, %1; cvt.u32.u64 %0, t; }" : "=r"(a) : "l"(p));
    return a;
}

__device__ __forceinline__ void ldm_x4(uint32_t& d0, uint32_t& d1, uint32_t& d2,
                                       uint32_t& d3, uint32_t addr) {
    asm volatile("ldmatrix.sync.aligned.m8n8.x4.shared.b16 {%0,%1,%2,%3}, [%4];"
                 : "=r"(d0), "=r"(d1), "=r"(d2), "=r"(d3) : "r"(addr));
}

__device__ __forceinline__ void mma_bf16(float* c, const uint32_t* a, const uint32_t* b) {
    asm volatile(
        "mma.sync.aligned.m16n8k16.row.col.f32.bf16.bf16.f32 "
        "{%0,%1,%2,%3}, {%4,%5,%6,%7}, {%8,%9}, {%0,%1,%2,%3};"
        : "+f"(c[0]), "+f"(c[1]), "+f"(c[2]), "+f"(c[3])
        : "r"(a[0]), "r"(a[1]), "r"(a[2]), "r"(a[3]), "r"(b[0]), "r"(b[1]));
}

__device__ __forceinline__ void cp16(uint32_t dst, const void* src) {
    asm volatile("cp.async.cg.shared.global [%0], [%1], 16;" :: "r"(dst), "l"(src));
}
#define CP_COMMIT() asm volatile("cp.async.commit_group;" ::: "memory")
#define CP_WAIT0()  asm volatile("cp.async.wait_group 0;" ::: "memory")

// ---------------- BF16 tensor-core GEMM (unchanged from R7) ------------------
#define BKb 64
#define LDB 72
#define TILEB (128 * LDB * 2)        // 18432 B
#define STGB  (2 * TILEB)            // 36864 B
#define GSM_TOT (2 * STGB)           // 73728 B

__global__ __launch_bounds__(256, 2)
void gemm_bf16(const __nv_bfloat16* __restrict__ A, const __nv_bfloat16* __restrict__ W,
               const float* __restrict__ b0, const float* __restrict__ b1,
               const float* __restrict__ b2, const float* __restrict__ resid,
               float* __restrict__ Cf,
               __nv_bfloat16* __restrict__ o0, __nv_bfloat16* __restrict__ o1,
               __nv_bfloat16* __restrict__ o2,
               int K, int actQK)
{
    extern __shared__ char smem[];
    const uint32_t smb = smem_u32(smem);

    const int tid  = threadIdx.x;
    const int lane = tid & 31;
    const int wid  = tid >> 5;
    const int wm   = wid & 1;
    const int wn   = wid >> 1;
    const int row0 = blockIdx.y * 128;
    const int col0 = blockIdx.x * 128;

    const int sel = col0 >> 10;
    const int lc0 = col0 & 1023;
    const float* bias = (sel == 0) ? b0 : ((sel == 1) ? b1 : b2);
    __nv_bfloat16* Cb = (sel == 0) ? o0 : ((sel == 1) ? o1 : o2);
    const int act = actQK && (sel < 2);

    const int rA = tid >> 3;
    const int kg = (tid & 7) * 8;

    const __nv_bfloat16* Ap0 = A + (size_t)(row0 + rA) * K + kg;
    const __nv_bfloat16* Ap1 = Ap0 + (size_t)32 * K;
    const __nv_bfloat16* Ap2 = Ap0 + (size_t)64 * K;
    const __nv_bfloat16* Ap3 = Ap0 + (size_t)96 * K;
    const __nv_bfloat16* Wp0 = W + (size_t)(col0 + rA) * K + kg;
    const __nv_bfloat16* Wp1 = Wp0 + (size_t)32 * K;
    const __nv_bfloat16* Wp2 = Wp0 + (size_t)64 * K;
    const __nv_bfloat16* Wp3 = Wp0 + (size_t)96 * K;

    const uint32_t st_off = (uint32_t)(rA * LDB + kg) * 2;
    const uint32_t rstep  = (uint32_t)(32 * LDB) * 2;

    const uint32_t a_lane = ((uint32_t)((wm * 64 + (lane & 15)) * LDB + (lane >> 4) * 8)) * 2;
    const uint32_t b_lane = ((uint32_t)((wn * 32 + ((lane >> 4) << 3) + (lane & 7)) * LDB
                                        + ((lane >> 3) & 1) * 8)) * 2;

    float acc[4][4][4] = {};
    const int nt = K / BKb;

    {
        const uint32_t sb = smb;
        cp16(sb + st_off,             Ap0);
        cp16(sb + st_off + rstep,     Ap1);
        cp16(sb + st_off + 2 * rstep, Ap2);
        cp16(sb + st_off + 3 * rstep, Ap3);
        cp16(sb + TILEB + st_off,             Wp0);
        cp16(sb + TILEB + st_off + rstep,     Wp1);
        cp16(sb + TILEB + st_off + 2 * rstep, Wp2);
        cp16(sb + TILEB + st_off + 3 * rstep, Wp3);
        CP_COMMIT();
    }

    for (int kt = 0; kt < nt; kt++) {
        CP_WAIT0();
        __syncthreads();

        if (kt + 1 < nt) {
            const int g = (kt + 1) * BKb;
            const uint32_t sb = smb + ((kt + 1) & 1) * STGB;
            cp16(sb + st_off,             Ap0 + g);
            cp16(sb + st_off + rstep,     Ap1 + g);
            cp16(sb + st_off + 2 * rstep, Ap2 + g);
            cp16(sb + st_off + 3 * rstep, Ap3 + g);
            cp16(sb + TILEB + st_off,             Wp0 + g);
            cp16(sb + TILEB + st_off + rstep,     Wp1 + g);
            cp16(sb + TILEB + st_off + 2 * rstep, Wp2 + g);
            cp16(sb + TILEB + st_off + 3 * rstep, Wp3 + g);
            CP_COMMIT();
        }

        const uint32_t ab = smb + (kt & 1) * STGB + a_lane;
        const uint32_t bb = smb + (kt & 1) * STGB + TILEB + b_lane;

        #pragma unroll
        for (int kk = 0; kk < BKb; kk += 16) {
            uint32_t af[4][4], bf[4][2];
            #pragma unroll
            for (int mf = 0; mf < 4; mf++)
                ldm_x4(af[mf][0], af[mf][1], af[mf][2], af[mf][3],
                       ab + (uint32_t)(mf * 16 * LDB + kk) * 2);
            #pragma unroll
            for (int np = 0; np < 2; np++)
                ldm_x4(bf[np * 2][0], bf[np * 2][1], bf[np * 2 + 1][0], bf[np * 2 + 1][1],
                       bb + (uint32_t)(np * 16 * LDB + kk) * 2);
            #pragma unroll
            for (int mf = 0; mf < 4; mf++)
                #pragma unroll
                for (int nf = 0; nf < 4; nf++)
                    mma_bf16(acc[mf][nf], af[mf], bf[nf]);
        }
    }

    #pragma unroll
    for (int mf = 0; mf < 4; mf++) {
        #pragma unroll
        for (int nf = 0; nf < 4; nf++) {
            const int r   = row0 + wm * 64 + mf * 16 + (lane >> 2);
            const int cgl = lc0 + wn * 32 + nf * 8 + 2 * (lane & 3);
            const float bb0 = bias[cgl], bb1 = bias[cgl + 1];
            #pragma unroll
            for (int half = 0; half < 2; half++) {
                const int rr = r + half * 8;
                float v0 = acc[mf][nf][half * 2 + 0] + bb0;
                float v1 = acc[mf][nf][half * 2 + 1] + bb1;
                if (resid) {
                    const float* rp = resid + (size_t)rr * Hdim + cgl;
                    v0 += rp[0];
                    v1 += rp[1];
                }
                if (act) {
                    v0 = (v0 > 0.f) ? (v0 + 1.f) : expf(v0);
                    v1 = (v1 > 0.f) ? (v1 + 1.f) : expf(v1);
                }
                if (Cf) {
                    *(float2*)(Cf + (size_t)rr * Hdim + cgl) = make_float2(v0, v1);
                } else {
                    *(__nv_bfloat162*)(Cb + (size_t)rr * Hdim + cgl) =
                        __floats2bfloat162_rn(v0, v1);
                }
            }
        }
    }
}

// ---------------- f32 -> bf16 conversion -------------------------------------
__global__ void __launch_bounds__(256)
conv_bf16(const float* __restrict__ in, __nv_bfloat16* __restrict__ out, int n4)
{
    const int i = blockIdx.x * blockDim.x + threadIdx.x;
    if (i < n4) {
        float4 v = ((const float4*)in)[i];
        __nv_bfloat162 lo = __floats2bfloat162_rn(v.x, v.y);
        __nv_bfloat162 hi = __floats2bfloat162_rn(v.z, v.w);
        uint2 u;
        u.x = *reinterpret_cast<uint32_t*>(&lo);
        u.y = *reinterpret_cast<uint32_t*>(&hi);
        ((uint2*)out)[i] = u;
    }
}

// ---------------- kv state via tensor cores ----------------------------------
// One CTA per bh. kv[m][d] = sum_s v[s][m]*k[s][d]; ksum[d] = sum_s k[s][d].
// k/v staged TRANSPOSED into smem (KT[d][s], VT[m][s]) so mma uses the same
// non-trans ldmatrix patterns as the main GEMM. No atomics, no pre-zeroing.
#define KVP 136   // smem pitch (bf16): 128 s-cols + 8 pad; row phase stride 17 -> conflict-free

__global__ __launch_bounds__(256)
void kv_tc(const __nv_bfloat16* __restrict__ k, const __nv_bfloat16* __restrict__ v,
           float* __restrict__ kv, float* __restrict__ ksum)
{
    __shared__ __nv_bfloat16 KT[64 * KVP];
    __shared__ __nv_bfloat16 VT[64 * KVP];
    __shared__ float ksacc[64];

    const int bh = blockIdx.x;
    const int b  = bh / NHEAD, h = bh % NHEAD;
    const int tid  = threadIdx.x;
    const int lane = tid & 31;
    const int wid  = tid >> 5;
    const int mi    = wid & 3;           // m-strip: 16*mi
    const int dbase = (wid >> 2) * 32;   // d rows 32 per warp-half

    const int trow = tid >> 3;           // local token 0..31 (then +32j)
    const int dgrp = tid & 7;            // 8-dim group

    const uint32_t ktb = smem_u32(KT);
    const uint32_t vtb = smem_u32(VT);

    // gmem base for this thread's segs: token trow+32j, dims dgrp*8..+7
    const size_t gbase = ((size_t)(b * Sseq) + trow) * Hdim + h * HDm + dgrp * 8;

    float ka[8] = {};
    float acc[4][4] = {};

    uint4 rk[4], rv[4], nk[4], nv[4];
    #pragma unroll
    for (int j = 0; j < 4; j++) {
        const size_t o = gbase + (size_t)(32 * j) * Hdim;
        rk[j] = *(const uint4*)(k + o);
        rv[j] = *(const uint4*)(v + o);
    }

    for (int tile = 0; tile < Sseq / 128; tile++) {
        if (tile + 1 < Sseq / 128) {
            const size_t o0 = gbase + (size_t)((tile + 1) * 128) * Hdim;
            #pragma unroll
            for (int j = 0; j < 4; j++) {
                const size_t o = o0 + (size_t)(32 * j) * Hdim;
                nk[j] = *(const uint4*)(k + o);
                nv[j] = *(const uint4*)(v + o);
            }
        }

        // transpose-store into smem + ksum partials
        #pragma unroll
        for (int j = 0; j < 4; j++) {
            const int tok = trow + 32 * j;
            const __nv_bfloat162* kp = (const __nv_bfloat162*)&rk[j];
            const __nv_bfloat162* vp = (const __nv_bfloat162*)&rv[j];
            #pragma unroll
            for (int p = 0; p < 4; p++) {
                const __nv_bfloat162 k2 = kp[p];
                const __nv_bfloat162 v2 = vp[p];
                const int d = dgrp * 8 + p * 2;
                KT[(d + 0) * KVP + tok] = k2.x;
                KT[(d + 1) * KVP + tok] = k2.y;
                VT[(d + 0) * KVP + tok] = v2.x;
                VT[(d + 1) * KVP + tok] = v2.y;
                ka[p * 2 + 0] += __bfloat162float(k2.x);
                ka[p * 2 + 1] += __bfloat162float(k2.y);
            }
        }
        __syncthreads();

        // mma over this 128-token tile
        #pragma unroll
        for (int st = 0; st < 8; st++) {
            const int scol = st * 16;
            uint32_t af[4], bf[4][2];
            ldm_x4(af[0], af[1], af[2], af[3],
                   vtb + (uint32_t)((16 * mi + (lane & 15)) * KVP + scol + (lane >> 4) * 8) * 2);
            #pragma unroll
            for (int np = 0; np < 2; np++)
                ldm_x4(bf[np * 2][0], bf[np * 2][1], bf[np * 2 + 1][0], bf[np * 2 + 1][1],
                       ktb + (uint32_t)((dbase + np * 16 + ((lane >> 4) << 3) + (lane & 7)) * KVP
                                        + scol + ((lane >> 3) & 1) * 8) * 2);
            #pragma unroll
            for (int n = 0; n < 4; n++)
                mma_bf16(acc[n], af, bf[n]);
        }
        __syncthreads();

        #pragma unroll
        for (int j = 0; j < 4; j++) { rk[j] = nk[j]; rv[j] = nv[j]; }
    }

    // write kv (no atomics)
    float* kvp = kv + (size_t)bh * HDm * HDm;
    #pragma unroll
    for (int n = 0; n < 4; n++) {
        const int d = dbase + 8 * n + 2 * (lane & 3);
        const int m0 = 16 * mi + (lane >> 2);
        *(float2*)(kvp + (m0 + 0) * HDm + d) = make_float2(acc[n][0], acc[n][1]);
        *(float2*)(kvp + (m0 + 8) * HDm + d) = make_float2(acc[n][2], acc[n][3]);
    }

    // ksum reduce via smem
    if (tid < 64) ksacc[tid] = 0.f;
    __syncthreads();
    #pragma unroll
    for (int p = 0; p < 8; p++)
        atomicAdd(&ksacc[dgrp * 8 + p], ka[p]);
    __syncthreads();
    if (tid < 64) ksum[bh * HDm + tid] = ksacc[tid];
}

// ---------------- ctx via tensor cores ---------------------------------------
// ctx[s][m] = (q[s,:] . kv[m,:]) * z[s],  z = 1/(q . (ksum+eps)), f32 normalizer.
#define QP 88   // smem pitch (bf16): rows 176B (11*16B) -> conflict-free ldmatrix, 16B-aligned

__global__ __launch_bounds__(256)
void ctx_tc(const __nv_bfloat16* __restrict__ q, const float* __restrict__ kv,
            const float* __restrict__ ksum, __nv_bfloat16* __restrict__ ctx)
{
    __shared__ __nv_bfloat16 KVb[64 * QP];
    __shared__ __nv_bfloat16 qsm[128 * QP];
    __shared__ float kse[64];
    __shared__ float zr[128];

    const int bh = blockIdx.x;
    const int b  = bh / NHEAD, h = bh % NHEAD;
    const int s0 = blockIdx.y * 128;
    const int tid  = threadIdx.x;
    const int lane = tid & 31;
    const int wid  = tid >> 5;

    const uint32_t kvb = smem_u32(KVb);
    const uint32_t qb_ = smem_u32(qsm);

    // stage kv (f32 -> bf16) and kse
    const float* kvg = kv + (size_t)bh * HDm * HDm;
    for (int i = tid; i < HDm * HDm; i += 256)
        KVb[(i >> 6) * QP + (i & 63)] = __float2bfloat16(kvg[i]);
    if (tid < 64) kse[tid] = ksum[bh * HDm + tid] + EPS_ATTN;

    // stage q: 128 tokens x 64 dims, uint4 segs
    {
        const int trow = tid >> 3;         // token 0..31 (+32j)
        const int dgrp = tid & 7;
        const size_t gb = ((size_t)(b * Sseq + s0) + trow) * Hdim + h * HDm + dgrp * 8;
        #pragma unroll
        for (int j = 0; j < 4; j++) {
            uint4 r = *(const uint4*)(q + gb + (size_t)(32 * j) * Hdim);
            *(uint4*)((char*)qsm + ((trow + 32 * j) * QP + dgrp * 8) * 2) = r;
        }
    }
    __syncthreads();

    // normalizer (f32)
    if (tid < 128) {
        float dot = 0.f;
        #pragma unroll 8
        for (int d = 0; d < HDm; d++)
            dot = fmaf(__bfloat162float(qsm[tid * QP + d]), kse[d], dot);
        zr[tid] = 1.f / dot;
    }
    __syncthreads();

    // mma: warp = one s16 strip; 8 n8 tiles over m, 4 k16 steps over d
    float acc[8][4] = {};
    const int srow = wid * 16;
    #pragma unroll
    for (int kk = 0; kk < 64; kk += 16) {
        uint32_t af[4], bf[8][2];
        ldm_x4(af[0], af[1], af[2], af[3],
               qb_ + (uint32_t)((srow + (lane & 15)) * QP + kk + (lane >> 4) * 8) * 2);
        #pragma unroll
        for (int np = 0; np < 4; np++)
            ldm_x4(bf[np * 2][0], bf[np * 2][1], bf[np * 2 + 1][0], bf[np * 2 + 1][1],
                   kvb + (uint32_t)((np * 16 + ((lane >> 4) << 3) + (lane & 7)) * QP
                                    + kk + ((lane >> 3) & 1) * 8) * 2);
        #pragma unroll
        for (int n = 0; n < 8; n++)
            mma_bf16(acc[n], af, bf[n]);
    }

    // epilogue: scale by z, write bf16
    const int r = lane >> 2;
    const int c = 2 * (lane & 3);
    #pragma unroll
    for (int half = 0; half < 2; half++) {
        const int tl = srow + r + half * 8;
        const float z = zr[tl];
        const size_t base = ((size_t)(b * Sseq + s0 + tl)) * Hdim + h * HDm;
        #pragma unroll
        for (int n = 0; n < 8; n++) {
            const int m = 8 * n + c;
            *(__nv_bfloat162*)(ctx + base + m) =
                __floats2bfloat162_rn(acc[n][half * 2 + 0] * z, acc[n][half * 2 + 1] * z);
        }
    }
}

// ---------------- LayerNorm over rows of 1024
__global__ __launch_bounds__(256)
void ln_kernel(const float* __restrict__ hs, const float* __restrict__ gamma,
               const float* __restrict__ beta, float* __restrict__ out)
{
    const int row = blockIdx.x;
    const int tid = threadIdx.x;
    const float4 v = ((const float4*)(hs + (size_t)row * Hdim))[tid];

    float s  = v.x + v.y + v.z + v.w;
    float sq = v.x * v.x + v.y * v.y + v.z * v.z + v.w * v.w;
    #pragma unroll
    for (int o = 16; o > 0; o >>= 1) {
        s  += __shfl_xor_sync(0xFFFFFFFFu, s, o);
        sq += __shfl_xor_sync(0xFFFFFFFFu, sq, o);
    }
    __shared__ float rs[8], rq[8];
    const int wid = tid >> 5, lane = tid & 31;
    if (lane == 0) { rs[wid] = s; rq[wid] = sq; }
    __syncthreads();
    float sum = 0.f, sumq = 0.f;
    #pragma unroll
    for (int i = 0; i < 8; i++) { sum += rs[i]; sumq += rq[i]; }

    const float mu   = sum * (1.f / Hdim);
    const float var  = sumq * (1.f / Hdim) - mu * mu;
    const float rstd = rsqrtf(var + EPS_LN);

    const float4 g4 = ((const float4*)gamma)[tid];
    const float4 b4 = ((const float4*)beta)[tid];
    float4 o;
    o.x = (v.x - mu) * rstd * g4.x + b4.x;
    o.y = (v.y - mu) * rstd * g4.y + b4.y;
    o.z = (v.z - mu) * rstd * g4.z + b4.z;
    o.w = (v.w - mu) * rstd * g4.w + b4.w;
    ((float4*)(out + (size_t)row * Hdim))[tid] = o;
}

// ---------------- launch ----------------------------------------------------
extern "C" void kernel_launch(void* const* d_in, const int* in_sizes, int n_in,
                              void* d_out, int out_size)
{
    const float* x     = (const float*)d_in[0];
    const float* Wq    = (const float*)d_in[2];
    const float* bq    = (const float*)d_in[3];
    const float* Wk    = (const float*)d_in[4];
    const float* bk    = (const float*)d_in[5];
    const float* Wv    = (const float*)d_in[6];
    const float* bv    = (const float*)d_in[7];
    const float* Wd    = (const float*)d_in[8];
    const float* bd    = (const float*)d_in[9];
    const float* gamma = (const float*)d_in[10];
    const float* beta  = (const float*)d_in[11];
    float* out = (float*)d_out;

    float *hs, *kv, *ksum;
    __nv_bfloat16 *qb, *kb, *vb, *xb, *cb, *wqkv, *wdb;
    cudaGetSymbolAddress((void**)&hs,   g_hs);
    cudaGetSymbolAddress((void**)&qb,   g_qb);
    cudaGetSymbolAddress((void**)&kb,   g_kb);
    cudaGetSymbolAddress((void**)&vb,   g_vb);
    cudaGetSymbolAddress((void**)&kv,   g_kv);
    cudaGetSymbolAddress((void**)&ksum, g_ksum);
    cudaGetSymbolAddress((void**)&xb,   g_xb);
    cudaGetSymbolAddress((void**)&cb,   g_cb);
    cudaGetSymbolAddress((void**)&wqkv, g_wqkv);
    cudaGetSymbolAddress((void**)&wdb,  g_wd);

    cudaFuncSetAttribute(gemm_bf16, cudaFuncAttributeMaxDynamicSharedMemorySize, GSM_TOT);

    const int xn4 = (int)((size_t)BSROWS * Hdim / 4);
    const int wn4 = Hdim * Hdim / 4;

    conv_bf16<<<xn4 / 256, 256>>>(x,  xb, xn4);
    conv_bf16<<<wn4 / 256, 256>>>(Wq, wqkv,                   wn4);
    conv_bf16<<<wn4 / 256, 256>>>(Wk, wqkv + Hdim * Hdim,     wn4);
    conv_bf16<<<wn4 / 256, 256>>>(Wv, wqkv + 2 * Hdim * Hdim, wn4);

    // fused QKV GEMM (+ elu+1 on q,k), bf16 outputs
    gemm_bf16<<<dim3(3 * Hdim / 128, BSROWS / 128), 256, GSM_TOT>>>(
        xb, wqkv, bq, bk, bv, nullptr, nullptr, qb, kb, vb, Hdim, 1);

    // kv state + ksum — tensor cores, one CTA per bh, no atomics/zeroing
    kv_tc<<<Bsz * NHEAD, 256>>>(kb, vb, kv, ksum);

    // ctx — tensor cores
    ctx_tc<<<dim3(Bsz * NHEAD, Sseq / 128), 256>>>(qb, kv, ksum, cb);

    // Wd conversion (deferred)
    conv_bf16<<<wn4 / 256, 256>>>(Wd, wdb, wn4);

    // output projection + bias + residual -> hs (f32)
    gemm_bf16<<<dim3(Hdim / 128, BSROWS / 128), 256, GSM_TOT>>>(
        cb, wdb, bd, bd, bd, x, hs, nullptr, nullptr, nullptr, Hdim, 0);

    // LayerNorm
    ln_kernel<<<BSROWS, 256>>>(hs, gamma, beta, out);
}

// round 9
// speedup vs baseline: 1.7408x; 1.0252x over previous
#include <cuda_runtime.h>
#include <cuda_bf16.h>
#include <cstdint>
#include <math.h>

#define Bsz 8
#define Sseq 4096
#define Hdim 1024
#define NHEAD 16
#define HDm 64
#define BSROWS (Bsz * Sseq)          // 32768
#define EPS_ATTN 1e-6f
#define EPS_LN 1e-12f

// ---------------- scratch (device globals; no allocation allowed) -----------
__device__ float g_hs[(size_t)BSROWS * Hdim];            // hs (f32)
__device__ __nv_bfloat16 g_qb[(size_t)BSROWS * Hdim];    // q bf16
__device__ __nv_bfloat16 g_kb[(size_t)BSROWS * Hdim];    // k bf16
__device__ __nv_bfloat16 g_vb[(size_t)BSROWS * Hdim];    // v bf16
__device__ float g_kv[Bsz * NHEAD * HDm * HDm];          // kv state [bh][m][d]
__device__ float g_ksum[Bsz * NHEAD * HDm];              // sum_s k  [bh][d]
__device__ __nv_bfloat16 g_xb[(size_t)BSROWS * Hdim];    // x in bf16
__device__ __nv_bfloat16 g_cb[(size_t)BSROWS * Hdim];    // ctx in bf16
__device__ __nv_bfloat16 g_wqkv[3 * Hdim * Hdim];        // Wq|Wk|Wv bf16
__device__ __nv_bfloat16 g_wd[Hdim * Hdim];

// ---------------- PTX helpers -------------------------------------------------
__device__ __forceinline__ uint32_t smem_u32(const void* p) {
    uint32_t a;
    asm("{ .reg .u64 t; cvta.to.shared.u64 t, %1; cvt.u32.u64 %0, t; }" : "=r"(a) : "l"(p));
    return a;
}

__device__ __forceinline__ void ldm_x4(uint32_t& d0, uint32_t& d1, uint32_t& d2,
                                       uint32_t& d3, uint32_t addr) {
    asm volatile("ldmatrix.sync.aligned.m8n8.x4.shared.b16 {%0,%1,%2,%3}, [%4];"
                 : "=r"(d0), "=r"(d1), "=r"(d2), "=r"(d3) : "r"(addr));
}

__device__ __forceinline__ void mma_bf16(float* c, const uint32_t* a, const uint32_t* b) {
    asm volatile(
        "mma.sync.aligned.m16n8k16.row.col.f32.bf16.bf16.f32 "
        "{%0,%1,%2,%3}, {%4,%5,%6,%7}, {%8,%9}, {%0,%1,%2,%3};"
        : "+f"(c[0]), "+f"(c[1]), "+f"(c[2]), "+f"(c[3])
        : "r"(a[0]), "r"(a[1]), "r"(a[2]), "r"(a[3]), "r"(b[0]), "r"(b[1]));
}

__device__ __forceinline__ void cp16(uint32_t dst, const void* src) {
    asm volatile("cp.async.cg.shared.global [%0], [%1], 16;" :: "r"(dst), "l"(src));
}
#define CP_COMMIT() asm volatile("cp.async.commit_group;" ::: "memory")
#define CP_WAIT0()  asm volatile("cp.async.wait_group 0;" ::: "memory")

// fast elu(x)+1: x>0 ? x+1 : exp(x)   (exp via single MUFU.EX2)
__device__ __forceinline__ float elu1(float x) {
    return (x > 0.f) ? (x + 1.f) : __expf(x);
}

// ---------------- BF16 tensor-core GEMM --------------------------------------
#define BKb 64
#define LDB 72
#define TILEB (128 * LDB * 2)        // 18432 B
#define STGB  (2 * TILEB)            // 36864 B
#define GSM_TOT (2 * STGB)           // 73728 B

__global__ __launch_bounds__(256, 2)
void gemm_bf16(const __nv_bfloat16* __restrict__ A, const __nv_bfloat16* __restrict__ W,
               const float* __restrict__ b0, const float* __restrict__ b1,
               const float* __restrict__ b2, const float* __restrict__ resid,
               float* __restrict__ Cf,
               __nv_bfloat16* __restrict__ o0, __nv_bfloat16* __restrict__ o1,
               __nv_bfloat16* __restrict__ o2,
               int K, int actQK)
{
    extern __shared__ char smem[];
    const uint32_t smb = smem_u32(smem);

    const int tid  = threadIdx.x;
    const int lane = tid & 31;
    const int wid  = tid >> 5;
    const int wm   = wid & 1;
    const int wn   = wid >> 1;
    const int row0 = blockIdx.y * 128;
    const int col0 = blockIdx.x * 128;

    const int sel = col0 >> 10;
    const int lc0 = col0 & 1023;
    const float* bias = (sel == 0) ? b0 : ((sel == 1) ? b1 : b2);
    __nv_bfloat16* Cb = (sel == 0) ? o0 : ((sel == 1) ? o1 : o2);
    const int act = actQK && (sel < 2);

    const int rA = tid >> 3;
    const int kg = (tid & 7) * 8;

    const __nv_bfloat16* Ap0 = A + (size_t)(row0 + rA) * K + kg;
    const __nv_bfloat16* Ap1 = Ap0 + (size_t)32 * K;
    const __nv_bfloat16* Ap2 = Ap0 + (size_t)64 * K;
    const __nv_bfloat16* Ap3 = Ap0 + (size_t)96 * K;
    const __nv_bfloat16* Wp0 = W + (size_t)(col0 + rA) * K + kg;
    const __nv_bfloat16* Wp1 = Wp0 + (size_t)32 * K;
    const __nv_bfloat16* Wp2 = Wp0 + (size_t)64 * K;
    const __nv_bfloat16* Wp3 = Wp0 + (size_t)96 * K;

    const uint32_t st_off = (uint32_t)(rA * LDB + kg) * 2;
    const uint32_t rstep  = (uint32_t)(32 * LDB) * 2;

    const uint32_t a_lane = ((uint32_t)((wm * 64 + (lane & 15)) * LDB + (lane >> 4) * 8)) * 2;
    const uint32_t b_lane = ((uint32_t)((wn * 32 + ((lane >> 4) << 3) + (lane & 7)) * LDB
                                        + ((lane >> 3) & 1) * 8)) * 2;

    float acc[4][4][4] = {};
    const int nt = K / BKb;

    {
        const uint32_t sb = smb;
        cp16(sb + st_off,             Ap0);
        cp16(sb + st_off + rstep,     Ap1);
        cp16(sb + st_off + 2 * rstep, Ap2);
        cp16(sb + st_off + 3 * rstep, Ap3);
        cp16(sb + TILEB + st_off,             Wp0);
        cp16(sb + TILEB + st_off + rstep,     Wp1);
        cp16(sb + TILEB + st_off + 2 * rstep, Wp2);
        cp16(sb + TILEB + st_off + 3 * rstep, Wp3);
        CP_COMMIT();
    }

    for (int kt = 0; kt < nt; kt++) {
        CP_WAIT0();
        __syncthreads();

        if (kt + 1 < nt) {
            const int g = (kt + 1) * BKb;
            const uint32_t sb = smb + ((kt + 1) & 1) * STGB;
            cp16(sb + st_off,             Ap0 + g);
            cp16(sb + st_off + rstep,     Ap1 + g);
            cp16(sb + st_off + 2 * rstep, Ap2 + g);
            cp16(sb + st_off + 3 * rstep, Ap3 + g);
            cp16(sb + TILEB + st_off,             Wp0 + g);
            cp16(sb + TILEB + st_off + rstep,     Wp1 + g);
            cp16(sb + TILEB + st_off + 2 * rstep, Wp2 + g);
            cp16(sb + TILEB + st_off + 3 * rstep, Wp3 + g);
            CP_COMMIT();
        }

        const uint32_t ab = smb + (kt & 1) * STGB + a_lane;
        const uint32_t bb = smb + (kt & 1) * STGB + TILEB + b_lane;

        #pragma unroll
        for (int kk = 0; kk < BKb; kk += 16) {
            uint32_t af[4][4], bf[4][2];
            #pragma unroll
            for (int mf = 0; mf < 4; mf++)
                ldm_x4(af[mf][0], af[mf][1], af[mf][2], af[mf][3],
                       ab + (uint32_t)(mf * 16 * LDB + kk) * 2);
            #pragma unroll
            for (int np = 0; np < 2; np++)
                ldm_x4(bf[np * 2][0], bf[np * 2][1], bf[np * 2 + 1][0], bf[np * 2 + 1][1],
                       bb + (uint32_t)(np * 16 * LDB + kk) * 2);
            #pragma unroll
            for (int mf = 0; mf < 4; mf++)
                #pragma unroll
                for (int nf = 0; nf < 4; nf++)
                    mma_bf16(acc[mf][nf], af[mf], bf[nf]);
        }
    }

    #pragma unroll
    for (int mf = 0; mf < 4; mf++) {
        #pragma unroll
        for (int nf = 0; nf < 4; nf++) {
            const int r   = row0 + wm * 64 + mf * 16 + (lane >> 2);
            const int cgl = lc0 + wn * 32 + nf * 8 + 2 * (lane & 3);
            const float bb0 = bias[cgl], bb1 = bias[cgl + 1];
            #pragma unroll
            for (int half = 0; half < 2; half++) {
                const int rr = r + half * 8;
                float v0 = acc[mf][nf][half * 2 + 0] + bb0;
                float v1 = acc[mf][nf][half * 2 + 1] + bb1;
                if (resid) {
                    const float* rp = resid + (size_t)rr * Hdim + cgl;
                    v0 += rp[0];
                    v1 += rp[1];
                }
                if (act) {
                    v0 = elu1(v0);
                    v1 = elu1(v1);
                }
                if (Cf) {
                    *(float2*)(Cf + (size_t)rr * Hdim + cgl) = make_float2(v0, v1);
                } else {
                    *(__nv_bfloat162*)(Cb + (size_t)rr * Hdim + cgl) =
                        __floats2bfloat162_rn(v0, v1);
                }
            }
        }
    }
}

// ---------------- f32 -> bf16 conversion -------------------------------------
__global__ void __launch_bounds__(256)
conv_bf16(const float* __restrict__ in, __nv_bfloat16* __restrict__ out, int n4)
{
    const int i = blockIdx.x * blockDim.x + threadIdx.x;
    if (i < n4) {
        float4 v = ((const float4*)in)[i];
        __nv_bfloat162 lo = __floats2bfloat162_rn(v.x, v.y);
        __nv_bfloat162 hi = __floats2bfloat162_rn(v.z, v.w);
        uint2 u;
        u.x = *reinterpret_cast<uint32_t*>(&lo);
        u.y = *reinterpret_cast<uint32_t*>(&hi);
        ((uint2*)out)[i] = u;
    }
}

// all 4 weight matrices in one launch; grid = 4 * (Hdim*Hdim/4/256)
__global__ void __launch_bounds__(256)
conv_w4(const float* __restrict__ Wq, const float* __restrict__ Wk,
        const float* __restrict__ Wv, const float* __restrict__ Wd,
        __nv_bfloat16* __restrict__ wqkv, __nv_bfloat16* __restrict__ wd)
{
    const int n4 = Hdim * Hdim / 4;
    const int nb = n4 / 256;                 // blocks per matrix
    const int j  = blockIdx.x / nb;          // which matrix
    const int i  = (blockIdx.x % nb) * 256 + threadIdx.x;
    const float* src = (j == 0) ? Wq : ((j == 1) ? Wk : ((j == 2) ? Wv : Wd));
    __nv_bfloat16* dst = (j < 3) ? (wqkv + (size_t)j * Hdim * Hdim) : wd;
    float4 v = ((const float4*)src)[i];
    __nv_bfloat162 lo = __floats2bfloat162_rn(v.x, v.y);
    __nv_bfloat162 hi = __floats2bfloat162_rn(v.z, v.w);
    uint2 u;
    u.x = *reinterpret_cast<uint32_t*>(&lo);
    u.y = *reinterpret_cast<uint32_t*>(&hi);
    ((uint2*)dst)[i] = u;
}

// ---------------- kv state via tensor cores ----------------------------------
#define KVP 136

__global__ __launch_bounds__(256)
void kv_tc(const __nv_bfloat16* __restrict__ k, const __nv_bfloat16* __restrict__ v,
           float* __restrict__ kv, float* __restrict__ ksum)
{
    __shared__ __nv_bfloat16 KT[64 * KVP];
    __shared__ __nv_bfloat16 VT[64 * KVP];
    __shared__ float ksacc[64];

    const int bh = blockIdx.x;
    const int b  = bh / NHEAD, h = bh % NHEAD;
    const int tid  = threadIdx.x;
    const int lane = tid & 31;
    const int wid  = tid >> 5;
    const int mi    = wid & 3;
    const int dbase = (wid >> 2) * 32;

    const int trow = tid >> 3;
    const int dgrp = tid & 7;

    const uint32_t ktb = smem_u32(KT);
    const uint32_t vtb = smem_u32(VT);

    const size_t gbase = ((size_t)(b * Sseq) + trow) * Hdim + h * HDm + dgrp * 8;

    float ka[8] = {};
    float acc[4][4] = {};

    uint4 rk[4], rv[4], nk[4], nv[4];
    #pragma unroll
    for (int j = 0; j < 4; j++) {
        const size_t o = gbase + (size_t)(32 * j) * Hdim;
        rk[j] = *(const uint4*)(k + o);
        rv[j] = *(const uint4*)(v + o);
    }

    for (int tile = 0; tile < Sseq / 128; tile++) {
        if (tile + 1 < Sseq / 128) {
            const size_t o0 = gbase + (size_t)((tile + 1) * 128) * Hdim;
            #pragma unroll
            for (int j = 0; j < 4; j++) {
                const size_t o = o0 + (size_t)(32 * j) * Hdim;
                nk[j] = *(const uint4*)(k + o);
                nv[j] = *(const uint4*)(v + o);
            }
        }

        #pragma unroll
        for (int j = 0; j < 4; j++) {
            const int tok = trow + 32 * j;
            const __nv_bfloat162* kp = (const __nv_bfloat162*)&rk[j];
            const __nv_bfloat162* vp = (const __nv_bfloat162*)&rv[j];
            #pragma unroll
            for (int p = 0; p < 4; p++) {
                const __nv_bfloat162 k2 = kp[p];
                const __nv_bfloat162 v2 = vp[p];
                const int d = dgrp * 8 + p * 2;
                KT[(d + 0) * KVP + tok] = k2.x;
                KT[(d + 1) * KVP + tok] = k2.y;
                VT[(d + 0) * KVP + tok] = v2.x;
                VT[(d + 1) * KVP + tok] = v2.y;
                ka[p * 2 + 0] += __bfloat162float(k2.x);
                ka[p * 2 + 1] += __bfloat162float(k2.y);
            }
        }
        __syncthreads();

        #pragma unroll
        for (int st = 0; st < 8; st++) {
            const int scol = st * 16;
            uint32_t af[4], bf[4][2];
            ldm_x4(af[0], af[1], af[2], af[3],
                   vtb + (uint32_t)((16 * mi + (lane & 15)) * KVP + scol + (lane >> 4) * 8) * 2);
            #pragma unroll
            for (int np = 0; np < 2; np++)
                ldm_x4(bf[np * 2][0], bf[np * 2][1], bf[np * 2 + 1][0], bf[np * 2 + 1][1],
                       ktb + (uint32_t)((dbase + np * 16 + ((lane >> 4) << 3) + (lane & 7)) * KVP
                                        + scol + ((lane >> 3) & 1) * 8) * 2);
            #pragma unroll
            for (int n = 0; n < 4; n++)
                mma_bf16(acc[n], af, bf[n]);
        }
        __syncthreads();

        #pragma unroll
        for (int j = 0; j < 4; j++) { rk[j] = nk[j]; rv[j] = nv[j]; }
    }

    float* kvp = kv + (size_t)bh * HDm * HDm;
    #pragma unroll
    for (int n = 0; n < 4; n++) {
        const int d = dbase + 8 * n + 2 * (lane & 3);
        const int m0 = 16 * mi + (lane >> 2);
        *(float2*)(kvp + (m0 + 0) * HDm + d) = make_float2(acc[n][0], acc[n][1]);
        *(float2*)(kvp + (m0 + 8) * HDm + d) = make_float2(acc[n][2], acc[n][3]);
    }

    if (tid < 64) ksacc[tid] = 0.f;
    __syncthreads();
    #pragma unroll
    for (int p = 0; p < 8; p++)
        atomicAdd(&ksacc[dgrp * 8 + p], ka[p]);
    __syncthreads();
    if (tid < 64) ksum[bh * HDm + tid] = ksacc[tid];
}

// ---------------- ctx via tensor cores ---------------------------------------
#define QP 88

__global__ __launch_bounds__(256)
void ctx_tc(const __nv_bfloat16* __restrict__ q, const float* __restrict__ kv,
            const float* __restrict__ ksum, __nv_bfloat16* __restrict__ ctx)
{
    __shared__ __nv_bfloat16 KVb[64 * QP];
    __shared__ __nv_bfloat16 qsm[128 * QP];
    __shared__ float kse[64];
    __shared__ float zr[128];

    const int bh = blockIdx.x;
    const int b  = bh / NHEAD, h = bh % NHEAD;
    const int s0 = blockIdx.y * 128;
    const int tid  = threadIdx.x;
    const int lane = tid & 31;
    const int wid  = tid >> 5;

    const uint32_t kvb = smem_u32(KVb);
    const uint32_t qb_ = smem_u32(qsm);

    const float* kvg = kv + (size_t)bh * HDm * HDm;
    for (int i = tid; i < HDm * HDm; i += 256)
        KVb[(i >> 6) * QP + (i & 63)] = __float2bfloat16(kvg[i]);
    if (tid < 64) kse[tid] = ksum[bh * HDm + tid] + EPS_ATTN;

    {
        const int trow = tid >> 3;
        const int dgrp = tid & 7;
        const size_t gb = ((size_t)(b * Sseq + s0) + trow) * Hdim + h * HDm + dgrp * 8;
        #pragma unroll
        for (int j = 0; j < 4; j++) {
            uint4 r = *(const uint4*)(q + gb + (size_t)(32 * j) * Hdim);
            *(uint4*)((char*)qsm + ((trow + 32 * j) * QP + dgrp * 8) * 2) = r;
        }
    }
    __syncthreads();

    if (tid < 128) {
        float dot = 0.f;
        #pragma unroll 8
        for (int d = 0; d < HDm; d++)
            dot = fmaf(__bfloat162float(qsm[tid * QP + d]), kse[d], dot);
        zr[tid] = 1.f / dot;
    }
    __syncthreads();

    float acc[8][4] = {};
    const int srow = wid * 16;
    #pragma unroll
    for (int kk = 0; kk < 64; kk += 16) {
        uint32_t af[4], bf[8][2];
        ldm_x4(af[0], af[1], af[2], af[3],
               qb_ + (uint32_t)((srow + (lane & 15)) * QP + kk + (lane >> 4) * 8) * 2);
        #pragma unroll
        for (int np = 0; np < 4; np++)
            ldm_x4(bf[np * 2][0], bf[np * 2][1], bf[np * 2 + 1][0], bf[np * 2 + 1][1],
                   kvb + (uint32_t)((np * 16 + ((lane >> 4) << 3) + (lane & 7)) * QP
                                    + kk + ((lane >> 3) & 1) * 8) * 2);
        #pragma unroll
        for (int n = 0; n < 8; n++)
            mma_bf16(acc[n], af, bf[n]);
    }

    const int r = lane >> 2;
    const int c = 2 * (lane & 3);
    #pragma unroll
    for (int half = 0; half < 2; half++) {
        const int tl = srow + r + half * 8;
        const float z = zr[tl];
        const size_t base = ((size_t)(b * Sseq + s0 + tl)) * Hdim + h * HDm;
        #pragma unroll
        for (int n = 0; n < 8; n++) {
            const int m = 8 * n + c;
            *(__nv_bfloat162*)(ctx + base + m) =
                __floats2bfloat162_rn(acc[n][half * 2 + 0] * z, acc[n][half * 2 + 1] * z);
        }
    }
}

// ---------------- LayerNorm over rows of 1024
__global__ __launch_bounds__(256)
void ln_kernel(const float* __restrict__ hs, const float* __restrict__ gamma,
               const float* __restrict__ beta, float* __restrict__ out)
{
    const int row = blockIdx.x;
    const int tid = threadIdx.x;
    const float4 v = ((const float4*)(hs + (size_t)row * Hdim))[tid];

    float s  = v.x + v.y + v.z + v.w;
    float sq = v.x * v.x + v.y * v.y + v.z * v.z + v.w * v.w;
    #pragma unroll
    for (int o = 16; o > 0; o >>= 1) {
        s  += __shfl_xor_sync(0xFFFFFFFFu, s, o);
        sq += __shfl_xor_sync(0xFFFFFFFFu, sq, o);
    }
    __shared__ float rs[8], rq[8];
    const int wid = tid >> 5, lane = tid & 31;
    if (lane == 0) { rs[wid] = s; rq[wid] = sq; }
    __syncthreads();
    float sum = 0.f, sumq = 0.f;
    #pragma unroll
    for (int i = 0; i < 8; i++) { sum += rs[i]; sumq += rq[i]; }

    const float mu   = sum * (1.f / Hdim);
    const float var  = sumq * (1.f / Hdim) - mu * mu;
    const float rstd = rsqrtf(var + EPS_LN);

    const float4 g4 = ((const float4*)gamma)[tid];
    const float4 b4 = ((const float4*)beta)[tid];
    float4 o;
    o.x = (v.x - mu) * rstd * g4.x + b4.x;
    o.y = (v.y - mu) * rstd * g4.y + b4.y;
    o.z = (v.z - mu) * rstd * g4.z + b4.z;
    o.w = (v.w - mu) * rstd * g4.w + b4.w;
    ((float4*)(out + (size_t)row * Hdim))[tid] = o;
}

// ---------------- launch ----------------------------------------------------
extern "C" void kernel_launch(void* const* d_in, const int* in_sizes, int n_in,
                              void* d_out, int out_size)
{
    const float* x     = (const float*)d_in[0];
    const float* Wq    = (const float*)d_in[2];
    const float* bq    = (const float*)d_in[3];
    const float* Wk    = (const float*)d_in[4];
    const float* bk    = (const float*)d_in[5];
    const float* Wv    = (const float*)d_in[6];
    const float* bv    = (const float*)d_in[7];
    const float* Wd    = (const float*)d_in[8];
    const float* bd    = (const float*)d_in[9];
    const float* gamma = (const float*)d_in[10];
    const float* beta  = (const float*)d_in[11];
    float* out = (float*)d_out;

    float *hs, *kv, *ksum;
    __nv_bfloat16 *qb, *kb, *vb, *xb, *cb, *wqkv, *wdb;
    cudaGetSymbolAddress((void**)&hs,   g_hs);
    cudaGetSymbolAddress((void**)&qb,   g_qb);
    cudaGetSymbolAddress((void**)&kb,   g_kb);
    cudaGetSymbolAddress((void**)&vb,   g_vb);
    cudaGetSymbolAddress((void**)&kv,   g_kv);
    cudaGetSymbolAddress((void**)&ksum, g_ksum);
    cudaGetSymbolAddress((void**)&xb,   g_xb);
    cudaGetSymbolAddress((void**)&cb,   g_cb);
    cudaGetSymbolAddress((void**)&wqkv, g_wqkv);
    cudaGetSymbolAddress((void**)&wdb,  g_wd);

    cudaFuncSetAttribute(gemm_bf16, cudaFuncAttributeMaxDynamicSharedMemorySize, GSM_TOT);

    const int xn4 = (int)((size_t)BSROWS * Hdim / 4);
    const int wn4 = Hdim * Hdim / 4;

    // idx0: x conversion; idx1: all 4 weight conversions
    conv_bf16<<<xn4 / 256, 256>>>(x, xb, xn4);
    conv_w4<<<4 * (wn4 / 256), 256>>>(Wq, Wk, Wv, Wd, wqkv, wdb);

    // idx2: fused QKV GEMM (+ elu+1 on q,k), bf16 outputs
    gemm_bf16<<<dim3(3 * Hdim / 128, BSROWS / 128), 256, GSM_TOT>>>(
        xb, wqkv, bq, bk, bv, nullptr, nullptr, qb, kb, vb, Hdim, 1);

    // idx3: kv state + ksum
    kv_tc<<<Bsz * NHEAD, 256>>>(kb, vb, kv, ksum);

    // idx4: ctx
    ctx_tc<<<dim3(Bsz * NHEAD, Sseq / 128), 256>>>(qb, kv, ksum, cb);

    // idx5: output projection + bias + residual -> hs (f32)
    gemm_bf16<<<dim3(Hdim / 128, BSROWS / 128), 256, GSM_TOT>>>(
        cb, wdb, bd, bd, bd, x, hs, nullptr, nullptr, nullptr, Hdim, 0);

    // idx6: LayerNorm
    ln_kernel<<<BSROWS, 256>>>(hs, gamma, beta, out);
}

// round 10
// speedup vs baseline: 1.8430x; 1.0587x over previous
#include <cuda_runtime.h>
#include <cuda_bf16.h>
#include <cstdint>
#include <math.h>

#define Bsz 8
#define Sseq 4096
#define Hdim 1024
#define NHEAD 16
#define HDm 64
#define BSROWS (Bsz * Sseq)          // 32768
#define EPS_ATTN 1e-6f
#define EPS_LN 1e-12f
#define SPLIT 4

// ---------------- scratch (device globals; no allocation allowed) -----------
__device__ float g_hs[(size_t)BSROWS * Hdim];            // hs (f32)
__device__ __nv_bfloat16 g_qb[(size_t)BSROWS * Hdim];    // q bf16
__device__ __nv_bfloat16 g_kb[(size_t)BSROWS * Hdim];    // k bf16
__device__ __nv_bfloat16 g_vb[(size_t)BSROWS * Hdim];    // v bf16
__device__ float g_kv[Bsz * NHEAD * HDm * HDm];          // kv state [bh][m][d]
__device__ float g_ksum[Bsz * NHEAD * HDm];              // sum_s k  [bh][d]
__device__ float g_kvp[SPLIT * Bsz * NHEAD * HDm * HDm]; // kv partials
__device__ float g_ksp[SPLIT * Bsz * NHEAD * HDm];       // ksum partials
__device__ __nv_bfloat16 g_xb[(size_t)BSROWS * Hdim];    // x in bf16
__device__ __nv_bfloat16 g_cb[(size_t)BSROWS * Hdim];    // ctx in bf16
__device__ __nv_bfloat16 g_wqkv[3 * Hdim * Hdim];        // Wq|Wk|Wv bf16
__device__ __nv_bfloat16 g_wd[Hdim * Hdim];

// ---------------- PTX helpers -------------------------------------------------
__device__ __forceinline__ uint32_t smem_u32(const void* p) {
    uint32_t a;
    asm("{ .reg .u64 t; cvta.to.shared.u64 t, %1; cvt.u32.u64 %0, t; }" : "=r"(a) : "l"(p));
    return a;
}

__device__ __forceinline__ void ldm_x4(uint32_t& d0, uint32_t& d1, uint32_t& d2,
                                       uint32_t& d3, uint32_t addr) {
    asm volatile("ldmatrix.sync.aligned.m8n8.x4.shared.b16 {%0,%1,%2,%3}, [%4];"
                 : "=r"(d0), "=r"(d1), "=r"(d2), "=r"(d3) : "r"(addr));
}

__device__ __forceinline__ void ldm_x4t(uint32_t& d0, uint32_t& d1, uint32_t& d2,
                                        uint32_t& d3, uint32_t addr) {
    asm volatile("ldmatrix.sync.aligned.m8n8.x4.trans.shared.b16 {%0,%1,%2,%3}, [%4];"
                 : "=r"(d0), "=r"(d1), "=r"(d2), "=r"(d3) : "r"(addr));
}

__device__ __forceinline__ void mma_bf16(float* c, const uint32_t* a, const uint32_t* b) {
    asm volatile(
        "mma.sync.aligned.m16n8k16.row.col.f32.bf16.bf16.f32 "
        "{%0,%1,%2,%3}, {%4,%5,%6,%7}, {%8,%9}, {%0,%1,%2,%3};"
        : "+f"(c[0]), "+f"(c[1]), "+f"(c[2]), "+f"(c[3])
        : "r"(a[0]), "r"(a[1]), "r"(a[2]), "r"(a[3]), "r"(b[0]), "r"(b[1]));
}

__device__ __forceinline__ void cp16(uint32_t dst, const void* src) {
    asm volatile("cp.async.cg.shared.global [%0], [%1], 16;" :: "r"(dst), "l"(src));
}
#define CP_COMMIT() asm volatile("cp.async.commit_group;" ::: "memory")
#define CP_WAIT0()  asm volatile("cp.async.wait_group 0;" ::: "memory")

__device__ __forceinline__ float elu1(float x) {
    return (x > 0.f) ? (x + 1.f) : __expf(x);
}

// ---------------- BF16 tensor-core GEMM (frozen from R9) ---------------------
#define BKb 64
#define LDB 72
#define TILEB (128 * LDB * 2)        // 18432 B
#define STGB  (2 * TILEB)            // 36864 B
#define GSM_TOT (2 * STGB)           // 73728 B

__global__ __launch_bounds__(256, 2)
void gemm_bf16(const __nv_bfloat16* __restrict__ A, const __nv_bfloat16* __restrict__ W,
               const float* __restrict__ b0, const float* __restrict__ b1,
               const float* __restrict__ b2, const float* __restrict__ resid,
               float* __restrict__ Cf,
               __nv_bfloat16* __restrict__ o0, __nv_bfloat16* __restrict__ o1,
               __nv_bfloat16* __restrict__ o2,
               int K, int actQK)
{
    extern __shared__ char smem[];
    const uint32_t smb = smem_u32(smem);

    const int tid  = threadIdx.x;
    const int lane = tid & 31;
    const int wid  = tid >> 5;
    const int wm   = wid & 1;
    const int wn   = wid >> 1;
    const int row0 = blockIdx.y * 128;
    const int col0 = blockIdx.x * 128;

    const int sel = col0 >> 10;
    const int lc0 = col0 & 1023;
    const float* bias = (sel == 0) ? b0 : ((sel == 1) ? b1 : b2);
    __nv_bfloat16* Cb = (sel == 0) ? o0 : ((sel == 1) ? o1 : o2);
    const int act = actQK && (sel < 2);

    const int rA = tid >> 3;
    const int kg = (tid & 7) * 8;

    const __nv_bfloat16* Ap0 = A + (size_t)(row0 + rA) * K + kg;
    const __nv_bfloat16* Ap1 = Ap0 + (size_t)32 * K;
    const __nv_bfloat16* Ap2 = Ap0 + (size_t)64 * K;
    const __nv_bfloat16* Ap3 = Ap0 + (size_t)96 * K;
    const __nv_bfloat16* Wp0 = W + (size_t)(col0 + rA) * K + kg;
    const __nv_bfloat16* Wp1 = Wp0 + (size_t)32 * K;
    const __nv_bfloat16* Wp2 = Wp0 + (size_t)64 * K;
    const __nv_bfloat16* Wp3 = Wp0 + (size_t)96 * K;

    const uint32_t st_off = (uint32_t)(rA * LDB + kg) * 2;
    const uint32_t rstep  = (uint32_t)(32 * LDB) * 2;

    const uint32_t a_lane = ((uint32_t)((wm * 64 + (lane & 15)) * LDB + (lane >> 4) * 8)) * 2;
    const uint32_t b_lane = ((uint32_t)((wn * 32 + ((lane >> 4) << 3) + (lane & 7)) * LDB
                                        + ((lane >> 3) & 1) * 8)) * 2;

    float acc[4][4][4] = {};
    const int nt = K / BKb;

    {
        const uint32_t sb = smb;
        cp16(sb + st_off,             Ap0);
        cp16(sb + st_off + rstep,     Ap1);
        cp16(sb + st_off + 2 * rstep, Ap2);
        cp16(sb + st_off + 3 * rstep, Ap3);
        cp16(sb + TILEB + st_off,             Wp0);
        cp16(sb + TILEB + st_off + rstep,     Wp1);
        cp16(sb + TILEB + st_off + 2 * rstep, Wp2);
        cp16(sb + TILEB + st_off + 3 * rstep, Wp3);
        CP_COMMIT();
    }

    for (int kt = 0; kt < nt; kt++) {
        CP_WAIT0();
        __syncthreads();

        if (kt + 1 < nt) {
            const int g = (kt + 1) * BKb;
            const uint32_t sb = smb + ((kt + 1) & 1) * STGB;
            cp16(sb + st_off,             Ap0 + g);
            cp16(sb + st_off + rstep,     Ap1 + g);
            cp16(sb + st_off + 2 * rstep, Ap2 + g);
            cp16(sb + st_off + 3 * rstep, Ap3 + g);
            cp16(sb + TILEB + st_off,             Wp0 + g);
            cp16(sb + TILEB + st_off + rstep,     Wp1 + g);
            cp16(sb + TILEB + st_off + 2 * rstep, Wp2 + g);
            cp16(sb + TILEB + st_off + 3 * rstep, Wp3 + g);
            CP_COMMIT();
        }

        const uint32_t ab = smb + (kt & 1) * STGB + a_lane;
        const uint32_t bb = smb + (kt & 1) * STGB + TILEB + b_lane;

        #pragma unroll
        for (int kk = 0; kk < BKb; kk += 16) {
            uint32_t af[4][4], bf[4][2];
            #pragma unroll
            for (int mf = 0; mf < 4; mf++)
                ldm_x4(af[mf][0], af[mf][1], af[mf][2], af[mf][3],
                       ab + (uint32_t)(mf * 16 * LDB + kk) * 2);
            #pragma unroll
            for (int np = 0; np < 2; np++)
                ldm_x4(bf[np * 2][0], bf[np * 2][1], bf[np * 2 + 1][0], bf[np * 2 + 1][1],
                       bb + (uint32_t)(np * 16 * LDB + kk) * 2);
            #pragma unroll
            for (int mf = 0; mf < 4; mf++)
                #pragma unroll
                for (int nf = 0; nf < 4; nf++)
                    mma_bf16(acc[mf][nf], af[mf], bf[nf]);
        }
    }

    #pragma unroll
    for (int mf = 0; mf < 4; mf++) {
        #pragma unroll
        for (int nf = 0; nf < 4; nf++) {
            const int r   = row0 + wm * 64 + mf * 16 + (lane >> 2);
            const int cgl = lc0 + wn * 32 + nf * 8 + 2 * (lane & 3);
            const float bb0 = bias[cgl], bb1 = bias[cgl + 1];
            #pragma unroll
            for (int half = 0; half < 2; half++) {
                const int rr = r + half * 8;
                float v0 = acc[mf][nf][half * 2 + 0] + bb0;
                float v1 = acc[mf][nf][half * 2 + 1] + bb1;
                if (resid) {
                    const float* rp = resid + (size_t)rr * Hdim + cgl;
                    v0 += rp[0];
                    v1 += rp[1];
                }
                if (act) {
                    v0 = elu1(v0);
                    v1 = elu1(v1);
                }
                if (Cf) {
                    *(float2*)(Cf + (size_t)rr * Hdim + cgl) = make_float2(v0, v1);
                } else {
                    *(__nv_bfloat162*)(Cb + (size_t)rr * Hdim + cgl) =
                        __floats2bfloat162_rn(v0, v1);
                }
            }
        }
    }
}

// ---------------- f32 -> bf16 conversion -------------------------------------
__global__ void __launch_bounds__(256)
conv_bf16(const float* __restrict__ in, __nv_bfloat16* __restrict__ out, int n4)
{
    const int i = blockIdx.x * blockDim.x + threadIdx.x;
    if (i < n4) {
        float4 v = ((const float4*)in)[i];
        __nv_bfloat162 lo = __floats2bfloat162_rn(v.x, v.y);
        __nv_bfloat162 hi = __floats2bfloat162_rn(v.z, v.w);
        uint2 u;
        u.x = *reinterpret_cast<uint32_t*>(&lo);
        u.y = *reinterpret_cast<uint32_t*>(&hi);
        ((uint2*)out)[i] = u;
    }
}

__global__ void __launch_bounds__(256)
conv_w4(const float* __restrict__ Wq, const float* __restrict__ Wk,
        const float* __restrict__ Wv, const float* __restrict__ Wd,
        __nv_bfloat16* __restrict__ wqkv, __nv_bfloat16* __restrict__ wd)
{
    const int n4 = Hdim * Hdim / 4;
    const int nb = n4 / 256;
    const int j  = blockIdx.x / nb;
    const int i  = (blockIdx.x % nb) * 256 + threadIdx.x;
    const float* src = (j == 0) ? Wq : ((j == 1) ? Wk : ((j == 2) ? Wv : Wd));
    __nv_bfloat16* dst = (j < 3) ? (wqkv + (size_t)j * Hdim * Hdim) : wd;
    float4 v = ((const float4*)src)[i];
    __nv_bfloat162 lo = __floats2bfloat162_rn(v.x, v.y);
    __nv_bfloat162 hi = __floats2bfloat162_rn(v.z, v.w);
    uint2 u;
    u.x = *reinterpret_cast<uint32_t*>(&lo);
    u.y = *reinterpret_cast<uint32_t*>(&hi);
    ((uint2*)dst)[i] = u;
}

// ---------------- kv state via tensor cores + ldmatrix.trans ------------------
// kv[m][d] = sum_s v[s][m]*k[s][d]. Tiles staged TOKEN-MAJOR (vector STS,
// conflict-light), transposed fragments come from ldmatrix.x4.trans.
// Split-S across SPLIT CTAs per bh; deterministic partial buffers.
#define KTP 72

__global__ __launch_bounds__(256)
void kv_tc(const __nv_bfloat16* __restrict__ k, const __nv_bfloat16* __restrict__ v,
           float* __restrict__ kvp, float* __restrict__ ksp)
{
    __shared__ __nv_bfloat16 KS[128 * KTP];
    __shared__ __nv_bfloat16 VS[128 * KTP];
    __shared__ float ksacc[64];

    const int bh = blockIdx.x;
    const int sp = blockIdx.y;
    const int b  = bh / NHEAD, h = bh % NHEAD;
    const int tid  = threadIdx.x;
    const int lane = tid & 31;
    const int wid  = tid >> 5;
    const int mi    = wid & 3;           // m strip 16*mi
    const int dbase = (wid >> 2) * 32;   // d strip

    const int rA = tid >> 3;             // token row 0..31
    const int kg = (tid & 7) * 8;        // dim seg

    const uint32_t ksb = smem_u32(KS);
    const uint32_t vsb = smem_u32(VS);
    const uint32_t sto = (uint32_t)(rA * KTP + kg) * 2;
    const uint32_t rstp = (uint32_t)(32 * KTP) * 2;

    // ldmatrix.trans lane addresses
    // A (V^T): s = scol + ((lane>>4)<<3) + (lane&7); mcol = 16*mi + (((lane>>3)&1)<<3)
    const uint32_t aoff = (uint32_t)(((lane >> 4) << 3) + (lane & 7)) * KTP * 2
                        + (uint32_t)(16 * mi + (((lane >> 3) & 1) << 3)) * 2;
    // B (K^T): s = scol + (((lane>>3)&1)<<3) + (lane&7); dcol = dbase + np*16 + ((lane>>4)<<3)
    const uint32_t boff = (uint32_t)((((lane >> 3) & 1) << 3) + (lane & 7)) * KTP * 2
                        + (uint32_t)(dbase + ((lane >> 4) << 3)) * 2;

    const int s_begin = sp * (Sseq / SPLIT);
    const size_t gbase = ((size_t)(b * Sseq + s_begin + rA)) * Hdim + h * HDm + kg;

    float ka[8] = {};
    float acc[4][4] = {};

    uint4 rk[4], rv[4], nk[4], nv[4];
    #pragma unroll
    for (int j = 0; j < 4; j++) {
        const size_t o = gbase + (size_t)(32 * j) * Hdim;
        rk[j] = *(const uint4*)(k + o);
        rv[j] = *(const uint4*)(v + o);
    }

    const int NT = Sseq / SPLIT / 128;   // 8 tiles of 128 tokens
    for (int tile = 0; tile < NT; tile++) {
        if (tile + 1 < NT) {
            const size_t o0 = gbase + (size_t)((tile + 1) * 128) * Hdim;
            #pragma unroll
            for (int j = 0; j < 4; j++) {
                const size_t o = o0 + (size_t)(32 * j) * Hdim;
                nk[j] = *(const uint4*)(k + o);
                nv[j] = *(const uint4*)(v + o);
            }
        }

        // stage token-major (vector stores) + ksum partials from registers
        #pragma unroll
        for (int j = 0; j < 4; j++) {
            *(uint4*)((char*)KS + sto + j * rstp) = rk[j];
            *(uint4*)((char*)VS + sto + j * rstp) = rv[j];
            const __nv_bfloat162* kp = (const __nv_bfloat162*)&rk[j];
            #pragma unroll
            for (int p = 0; p < 4; p++) {
                ka[p * 2 + 0] += __bfloat162float(kp[p].x);
                ka[p * 2 + 1] += __bfloat162float(kp[p].y);
            }
        }
        __syncthreads();

        #pragma unroll
        for (int st = 0; st < 8; st++) {
            const uint32_t srow = (uint32_t)(st * 16) * KTP * 2;
            uint32_t af[4], bf[4][2];
            ldm_x4t(af[0], af[1], af[2], af[3], vsb + srow + aoff);
            #pragma unroll
            for (int np = 0; np < 2; np++)
                ldm_x4t(bf[np * 2][0], bf[np * 2][1], bf[np * 2 + 1][0], bf[np * 2 + 1][1],
                        ksb + srow + boff + (uint32_t)(np * 16) * 2);
            #pragma unroll
            for (int n = 0; n < 4; n++)
                mma_bf16(acc[n], af, bf[n]);
        }
        __syncthreads();

        #pragma unroll
        for (int j = 0; j < 4; j++) { rk[j] = nk[j]; rv[j] = nv[j]; }
    }

    // write kv partial (no atomics)
    float* kvo = kvp + ((size_t)sp * Bsz * NHEAD + bh) * HDm * HDm;
    #pragma unroll
    for (int n = 0; n < 4; n++) {
        const int d = dbase + 8 * n + 2 * (lane & 3);
        const int m0 = 16 * mi + (lane >> 2);
        *(float2*)(kvo + (m0 + 0) * HDm + d) = make_float2(acc[n][0], acc[n][1]);
        *(float2*)(kvo + (m0 + 8) * HDm + d) = make_float2(acc[n][2], acc[n][3]);
    }

    // ksum partial via smem reduce
    if (tid < 64) ksacc[tid] = 0.f;
    __syncthreads();
    #pragma unroll
    for (int p = 0; p < 8; p++)
        atomicAdd(&ksacc[kg + p], ka[p]);
    __syncthreads();
    if (tid < 64) ksp[((size_t)sp * Bsz * NHEAD + bh) * HDm + tid] = ksacc[tid];
}

// reduce SPLIT partials -> kv, ksum (deterministic)
__global__ void __launch_bounds__(256)
kv_reduce(const float* __restrict__ kvp, const float* __restrict__ ksp,
          float* __restrict__ kv, float* __restrict__ ksum)
{
    const int KVN = Bsz * NHEAD * HDm * HDm;   // 524288
    const int KSN = Bsz * NHEAD * HDm;         // 8192
    const int i = blockIdx.x * 256 + threadIdx.x;
    if (i < KVN) {
        float s = 0.f;
        #pragma unroll
        for (int p = 0; p < SPLIT; p++) s += kvp[(size_t)p * KVN + i];
        kv[i] = s;
    } else if (i < KVN + KSN) {
        const int j = i - KVN;
        float s = 0.f;
        #pragma unroll
        for (int p = 0; p < SPLIT; p++) s += ksp[(size_t)p * KSN + j];
        ksum[j] = s;
    }
}

// ---------------- ctx via tensor cores (unchanged) ----------------------------
#define QP 88

__global__ __launch_bounds__(256)
void ctx_tc(const __nv_bfloat16* __restrict__ q, const float* __restrict__ kv,
            const float* __restrict__ ksum, __nv_bfloat16* __restrict__ ctx)
{
    __shared__ __nv_bfloat16 KVb[64 * QP];
    __shared__ __nv_bfloat16 qsm[128 * QP];
    __shared__ float kse[64];
    __shared__ float zr[128];

    const int bh = blockIdx.x;
    const int b  = bh / NHEAD, h = bh % NHEAD;
    const int s0 = blockIdx.y * 128;
    const int tid  = threadIdx.x;
    const int lane = tid & 31;
    const int wid  = tid >> 5;

    const uint32_t kvb = smem_u32(KVb);
    const uint32_t qb_ = smem_u32(qsm);

    const float* kvg = kv + (size_t)bh * HDm * HDm;
    for (int i = tid; i < HDm * HDm; i += 256)
        KVb[(i >> 6) * QP + (i & 63)] = __float2bfloat16(kvg[i]);
    if (tid < 64) kse[tid] = ksum[bh * HDm + tid] + EPS_ATTN;

    {
        const int trow = tid >> 3;
        const int dgrp = tid & 7;
        const size_t gb = ((size_t)(b * Sseq + s0) + trow) * Hdim + h * HDm + dgrp * 8;
        #pragma unroll
        for (int j = 0; j < 4; j++) {
            uint4 r = *(const uint4*)(q + gb + (size_t)(32 * j) * Hdim);
            *(uint4*)((char*)qsm + ((trow + 32 * j) * QP + dgrp * 8) * 2) = r;
        }
    }
    __syncthreads();

    if (tid < 128) {
        float dot = 0.f;
        #pragma unroll 8
        for (int d = 0; d < HDm; d++)
            dot = fmaf(__bfloat162float(qsm[tid * QP + d]), kse[d], dot);
        zr[tid] = 1.f / dot;
    }
    __syncthreads();

    float acc[8][4] = {};
    const int srow = wid * 16;
    #pragma unroll
    for (int kk = 0; kk < 64; kk += 16) {
        uint32_t af[4], bf[8][2];
        ldm_x4(af[0], af[1], af[2], af[3],
               qb_ + (uint32_t)((srow + (lane & 15)) * QP + kk + (lane >> 4) * 8) * 2);
        #pragma unroll
        for (int np = 0; np < 4; np++)
            ldm_x4(bf[np * 2][0], bf[np * 2][1], bf[np * 2 + 1][0], bf[np * 2 + 1][1],
                   kvb + (uint32_t)((np * 16 + ((lane >> 4) << 3) + (lane & 7)) * QP
                                    + kk + ((lane >> 3) & 1) * 8) * 2);
        #pragma unroll
        for (int n = 0; n < 8; n++)
            mma_bf16(acc[n], af, bf[n]);
    }

    const int r = lane >> 2;
    const int c = 2 * (lane & 3);
    #pragma unroll
    for (int half = 0; half < 2; half++) {
        const int tl = srow + r + half * 8;
        const float z = zr[tl];
        const size_t base = ((size_t)(b * Sseq + s0 + tl)) * Hdim + h * HDm;
        #pragma unroll
        for (int n = 0; n < 8; n++) {
            const int m = 8 * n + c;
            *(__nv_bfloat162*)(ctx + base + m) =
                __floats2bfloat162_rn(acc[n][half * 2 + 0] * z, acc[n][half * 2 + 1] * z);
        }
    }
}

// ---------------- LayerNorm over rows of 1024
__global__ __launch_bounds__(256)
void ln_kernel(const float* __restrict__ hs, const float* __restrict__ gamma,
               const float* __restrict__ beta, float* __restrict__ out)
{
    const int row = blockIdx.x;
    const int tid = threadIdx.x;
    const float4 v = ((const float4*)(hs + (size_t)row * Hdim))[tid];

    float s  = v.x + v.y + v.z + v.w;
    float sq = v.x * v.x + v.y * v.y + v.z * v.z + v.w * v.w;
    #pragma unroll
    for (int o = 16; o > 0; o >>= 1) {
        s  += __shfl_xor_sync(0xFFFFFFFFu, s, o);
        sq += __shfl_xor_sync(0xFFFFFFFFu, sq, o);
    }
    __shared__ float rs[8], rq[8];
    const int wid = tid >> 5, lane = tid & 31;
    if (lane == 0) { rs[wid] = s; rq[wid] = sq; }
    __syncthreads();
    float sum = 0.f, sumq = 0.f;
    #pragma unroll
    for (int i = 0; i < 8; i++) { sum += rs[i]; sumq += rq[i]; }

    const float mu   = sum * (1.f / Hdim);
    const float var  = sumq * (1.f / Hdim) - mu * mu;
    const float rstd = rsqrtf(var + EPS_LN);

    const float4 g4 = ((const float4*)gamma)[tid];
    const float4 b4 = ((const float4*)beta)[tid];
    float4 o;
    o.x = (v.x - mu) * rstd * g4.x + b4.x;
    o.y = (v.y - mu) * rstd * g4.y + b4.y;
    o.z = (v.z - mu) * rstd * g4.z + b4.z;
    o.w = (v.w - mu) * rstd * g4.w + b4.w;
    ((float4*)(out + (size_t)row * Hdim))[tid] = o;
}

// ---------------- launch ----------------------------------------------------
extern "C" void kernel_launch(void* const* d_in, const int* in_sizes, int n_in,
                              void* d_out, int out_size)
{
    const float* x     = (const float*)d_in[0];
    const float* Wq    = (const float*)d_in[2];
    const float* bq    = (const float*)d_in[3];
    const float* Wk    = (const float*)d_in[4];
    const float* bk    = (const float*)d_in[5];
    const float* Wv    = (const float*)d_in[6];
    const float* bv    = (const float*)d_in[7];
    const float* Wd    = (const float*)d_in[8];
    const float* bd    = (const float*)d_in[9];
    const float* gamma = (const float*)d_in[10];
    const float* beta  = (const float*)d_in[11];
    float* out = (float*)d_out;

    float *hs, *kv, *ksum, *kvp, *ksp;
    __nv_bfloat16 *qb, *kb, *vb, *xb, *cb, *wqkv, *wdb;
    cudaGetSymbolAddress((void**)&hs,   g_hs);
    cudaGetSymbolAddress((void**)&qb,   g_qb);
    cudaGetSymbolAddress((void**)&kb,   g_kb);
    cudaGetSymbolAddress((void**)&vb,   g_vb);
    cudaGetSymbolAddress((void**)&kv,   g_kv);
    cudaGetSymbolAddress((void**)&ksum, g_ksum);
    cudaGetSymbolAddress((void**)&kvp,  g_kvp);
    cudaGetSymbolAddress((void**)&ksp,  g_ksp);
    cudaGetSymbolAddress((void**)&xb,   g_xb);
    cudaGetSymbolAddress((void**)&cb,   g_cb);
    cudaGetSymbolAddress((void**)&wqkv, g_wqkv);
    cudaGetSymbolAddress((void**)&wdb,  g_wd);

    cudaFuncSetAttribute(gemm_bf16, cudaFuncAttributeMaxDynamicSharedMemorySize, GSM_TOT);

    const int xn4 = (int)((size_t)BSROWS * Hdim / 4);
    const int wn4 = Hdim * Hdim / 4;

    conv_bf16<<<xn4 / 256, 256>>>(x, xb, xn4);
    conv_w4<<<4 * (wn4 / 256), 256>>>(Wq, Wk, Wv, Wd, wqkv, wdb);

    // fused QKV GEMM (+ elu+1 on q,k), bf16 outputs
    gemm_bf16<<<dim3(3 * Hdim / 128, BSROWS / 128), 256, GSM_TOT>>>(
        xb, wqkv, bq, bk, bv, nullptr, nullptr, qb, kb, vb, Hdim, 1);

    // kv state + ksum — split-S, ldmatrix.trans, partial buffers
    kv_tc<<<dim3(Bsz * NHEAD, SPLIT), 256>>>(kb, vb, kvp, ksp);
    {
        const int n = Bsz * NHEAD * HDm * HDm + Bsz * NHEAD * HDm;
        kv_reduce<<<(n + 255) / 256, 256>>>(kvp, ksp, kv, ksum);
    }

    // ctx
    ctx_tc<<<dim3(Bsz * NHEAD, Sseq / 128), 256>>>(qb, kv, ksum, cb);

    // output projection + bias + residual -> hs (f32)
    gemm_bf16<<<dim3(Hdim / 128, BSROWS / 128), 256, GSM_TOT>>>(
        cb, wdb, bd, bd, bd, x, hs, nullptr, nullptr, nullptr, Hdim, 0);

    // LayerNorm
    ln_kernel<<<BSROWS, 256>>>(hs, gamma, beta, out);
}

// round 11
// speedup vs baseline: 1.8536x; 1.0057x over previous
#include <cuda_runtime.h>
#include <cuda_bf16.h>
#include <cstdint>
#include <math.h>

#define Bsz 8
#define Sseq 4096
#define Hdim 1024
#define NHEAD 16
#define HDm 64
#define BSROWS (Bsz * Sseq)          // 32768
#define EPS_ATTN 1e-6f
#define EPS_LN 1e-12f
#define SPLIT 8

// ---------------- scratch (device globals; no allocation allowed) -----------
__device__ float g_hs[(size_t)BSROWS * Hdim];            // hs (f32)
__device__ __nv_bfloat16 g_qb[(size_t)BSROWS * Hdim];    // q bf16
__device__ __nv_bfloat16 g_kb[(size_t)BSROWS * Hdim];    // k bf16
__device__ __nv_bfloat16 g_vb[(size_t)BSROWS * Hdim];    // v bf16
__device__ float g_kv[Bsz * NHEAD * HDm * HDm];          // kv state [bh][m][d]
__device__ float g_ksum[Bsz * NHEAD * HDm];              // sum_s k  [bh][d]
__device__ float g_kvp[SPLIT * Bsz * NHEAD * HDm * HDm]; // kv partials
__device__ float g_ksp[SPLIT * Bsz * NHEAD * HDm];       // ksum partials
__device__ __nv_bfloat16 g_xb[(size_t)BSROWS * Hdim];    // x in bf16
__device__ __nv_bfloat16 g_cb[(size_t)BSROWS * Hdim];    // ctx in bf16
__device__ __nv_bfloat16 g_wqkv[3 * Hdim * Hdim];        // Wq|Wk|Wv bf16
__device__ __nv_bfloat16 g_wd[Hdim * Hdim];

// ---------------- PTX helpers -------------------------------------------------
__device__ __forceinline__ uint32_t smem_u32(const void* p) {
    uint32_t a;
    asm("{ .reg .u64 t; cvta.to.shared.u64 t, %1; cvt.u32.u64 %0, t; }" : "=r"(a) : "l"(p));
    return a;
}

__device__ __forceinline__ void ldm_x4(uint32_t& d0, uint32_t& d1, uint32_t& d2,
                                       uint32_t& d3, uint32_t addr) {
    asm volatile("ldmatrix.sync.aligned.m8n8.x4.shared.b16 {%0,%1,%2,%3}, [%4];"
                 : "=r"(d0), "=r"(d1), "=r"(d2), "=r"(d3) : "r"(addr));
}

__device__ __forceinline__ void ldm_x4t(uint32_t& d0, uint32_t& d1, uint32_t& d2,
                                        uint32_t& d3, uint32_t addr) {
    asm volatile("ldmatrix.sync.aligned.m8n8.x4.trans.shared.b16 {%0,%1,%2,%3}, [%4];"
                 : "=r"(d0), "=r"(d1), "=r"(d2), "=r"(d3) : "r"(addr));
}

__device__ __forceinline__ void mma_bf16(float* c, const uint32_t* a, const uint32_t* b) {
    asm volatile(
        "mma.sync.aligned.m16n8k16.row.col.f32.bf16.bf16.f32 "
        "{%0,%1,%2,%3}, {%4,%5,%6,%7}, {%8,%9}, {%0,%1,%2,%3};"
        : "+f"(c[0]), "+f"(c[1]), "+f"(c[2]), "+f"(c[3])
        : "r"(a[0]), "r"(a[1]), "r"(a[2]), "r"(a[3]), "r"(b[0]), "r"(b[1]));
}

__device__ __forceinline__ void cp16(uint32_t dst, const void* src) {
    asm volatile("cp.async.cg.shared.global [%0], [%1], 16;" :: "r"(dst), "l"(src));
}
#define CP_COMMIT() asm volatile("cp.async.commit_group;" ::: "memory")
#define CP_WAIT0()  asm volatile("cp.async.wait_group 0;" ::: "memory")

__device__ __forceinline__ float elu1(float x) {
    return (x > 0.f) ? (x + 1.f) : __expf(x);
}

// ---------------- BF16 tensor-core GEMM (frozen) ------------------------------
#define BKb 64
#define LDB 72
#define TILEB (128 * LDB * 2)        // 18432 B
#define STGB  (2 * TILEB)            // 36864 B
#define GSM_TOT (2 * STGB)           // 73728 B

__global__ __launch_bounds__(256, 2)
void gemm_bf16(const __nv_bfloat16* __restrict__ A, const __nv_bfloat16* __restrict__ W,
               const float* __restrict__ b0, const float* __restrict__ b1,
               const float* __restrict__ b2, const float* __restrict__ resid,
               float* __restrict__ Cf,
               __nv_bfloat16* __restrict__ o0, __nv_bfloat16* __restrict__ o1,
               __nv_bfloat16* __restrict__ o2,
               int K, int actQK)
{
    extern __shared__ char smem[];
    const uint32_t smb = smem_u32(smem);

    const int tid  = threadIdx.x;
    const int lane = tid & 31;
    const int wid  = tid >> 5;
    const int wm   = wid & 1;
    const int wn   = wid >> 1;
    const int row0 = blockIdx.y * 128;
    const int col0 = blockIdx.x * 128;

    const int sel = col0 >> 10;
    const int lc0 = col0 & 1023;
    const float* bias = (sel == 0) ? b0 : ((sel == 1) ? b1 : b2);
    __nv_bfloat16* Cb = (sel == 0) ? o0 : ((sel == 1) ? o1 : o2);
    const int act = actQK && (sel < 2);

    const int rA = tid >> 3;
    const int kg = (tid & 7) * 8;

    const __nv_bfloat16* Ap0 = A + (size_t)(row0 + rA) * K + kg;
    const __nv_bfloat16* Ap1 = Ap0 + (size_t)32 * K;
    const __nv_bfloat16* Ap2 = Ap0 + (size_t)64 * K;
    const __nv_bfloat16* Ap3 = Ap0 + (size_t)96 * K;
    const __nv_bfloat16* Wp0 = W + (size_t)(col0 + rA) * K + kg;
    const __nv_bfloat16* Wp1 = Wp0 + (size_t)32 * K;
    const __nv_bfloat16* Wp2 = Wp0 + (size_t)64 * K;
    const __nv_bfloat16* Wp3 = Wp0 + (size_t)96 * K;

    const uint32_t st_off = (uint32_t)(rA * LDB + kg) * 2;
    const uint32_t rstep  = (uint32_t)(32 * LDB) * 2;

    const uint32_t a_lane = ((uint32_t)((wm * 64 + (lane & 15)) * LDB + (lane >> 4) * 8)) * 2;
    const uint32_t b_lane = ((uint32_t)((wn * 32 + ((lane >> 4) << 3) + (lane & 7)) * LDB
                                        + ((lane >> 3) & 1) * 8)) * 2;

    float acc[4][4][4] = {};
    const int nt = K / BKb;

    {
        const uint32_t sb = smb;
        cp16(sb + st_off,             Ap0);
        cp16(sb + st_off + rstep,     Ap1);
        cp16(sb + st_off + 2 * rstep, Ap2);
        cp16(sb + st_off + 3 * rstep, Ap3);
        cp16(sb + TILEB + st_off,             Wp0);
        cp16(sb + TILEB + st_off + rstep,     Wp1);
        cp16(sb + TILEB + st_off + 2 * rstep, Wp2);
        cp16(sb + TILEB + st_off + 3 * rstep, Wp3);
        CP_COMMIT();
    }

    for (int kt = 0; kt < nt; kt++) {
        CP_WAIT0();
        __syncthreads();

        if (kt + 1 < nt) {
            const int g = (kt + 1) * BKb;
            const uint32_t sb = smb + ((kt + 1) & 1) * STGB;
            cp16(sb + st_off,             Ap0 + g);
            cp16(sb + st_off + rstep,     Ap1 + g);
            cp16(sb + st_off + 2 * rstep, Ap2 + g);
            cp16(sb + st_off + 3 * rstep, Ap3 + g);
            cp16(sb + TILEB + st_off,             Wp0 + g);
            cp16(sb + TILEB + st_off + rstep,     Wp1 + g);
            cp16(sb + TILEB + st_off + 2 * rstep, Wp2 + g);
            cp16(sb + TILEB + st_off + 3 * rstep, Wp3 + g);
            CP_COMMIT();
        }

        const uint32_t ab = smb + (kt & 1) * STGB + a_lane;
        const uint32_t bb = smb + (kt & 1) * STGB + TILEB + b_lane;

        #pragma unroll
        for (int kk = 0; kk < BKb; kk += 16) {
            uint32_t af[4][4], bf[4][2];
            #pragma unroll
            for (int mf = 0; mf < 4; mf++)
                ldm_x4(af[mf][0], af[mf][1], af[mf][2], af[mf][3],
                       ab + (uint32_t)(mf * 16 * LDB + kk) * 2);
            #pragma unroll
            for (int np = 0; np < 2; np++)
                ldm_x4(bf[np * 2][0], bf[np * 2][1], bf[np * 2 + 1][0], bf[np * 2 + 1][1],
                       bb + (uint32_t)(np * 16 * LDB + kk) * 2);
            #pragma unroll
            for (int mf = 0; mf < 4; mf++)
                #pragma unroll
                for (int nf = 0; nf < 4; nf++)
                    mma_bf16(acc[mf][nf], af[mf], bf[nf]);
        }
    }

    #pragma unroll
    for (int mf = 0; mf < 4; mf++) {
        #pragma unroll
        for (int nf = 0; nf < 4; nf++) {
            const int r   = row0 + wm * 64 + mf * 16 + (lane >> 2);
            const int cgl = lc0 + wn * 32 + nf * 8 + 2 * (lane & 3);
            const float bb0 = bias[cgl], bb1 = bias[cgl + 1];
            #pragma unroll
            for (int half = 0; half < 2; half++) {
                const int rr = r + half * 8;
                float v0 = acc[mf][nf][half * 2 + 0] + bb0;
                float v1 = acc[mf][nf][half * 2 + 1] + bb1;
                if (resid) {
                    const float* rp = resid + (size_t)rr * Hdim + cgl;
                    v0 += rp[0];
                    v1 += rp[1];
                }
                if (act) {
                    v0 = elu1(v0);
                    v1 = elu1(v1);
                }
                if (Cf) {
                    *(float2*)(Cf + (size_t)rr * Hdim + cgl) = make_float2(v0, v1);
                } else {
                    *(__nv_bfloat162*)(Cb + (size_t)rr * Hdim + cgl) =
                        __floats2bfloat162_rn(v0, v1);
                }
            }
        }
    }
}

// ---------------- f32 -> bf16 conversions -------------------------------------
__global__ void __launch_bounds__(256)
conv_bf16(const float* __restrict__ in, __nv_bfloat16* __restrict__ out, int n4)
{
    const int i = blockIdx.x * blockDim.x + threadIdx.x;
    if (i < n4) {
        float4 v = ((const float4*)in)[i];
        __nv_bfloat162 lo = __floats2bfloat162_rn(v.x, v.y);
        __nv_bfloat162 hi = __floats2bfloat162_rn(v.z, v.w);
        uint2 u;
        u.x = *reinterpret_cast<uint32_t*>(&lo);
        u.y = *reinterpret_cast<uint32_t*>(&hi);
        ((uint2*)out)[i] = u;
    }
}

// 3 QKV weight matrices in one launch
__global__ void __launch_bounds__(256)
conv_w3(const float* __restrict__ Wq, const float* __restrict__ Wk,
        const float* __restrict__ Wv, __nv_bfloat16* __restrict__ wqkv)
{
    const int n4 = Hdim * Hdim / 4;
    const int nb = n4 / 256;
    const int j  = blockIdx.x / nb;
    const int i  = (blockIdx.x % nb) * 256 + threadIdx.x;
    const float* src = (j == 0) ? Wq : ((j == 1) ? Wk : Wv);
    __nv_bfloat16* dst = wqkv + (size_t)j * Hdim * Hdim;
    float4 v = ((const float4*)src)[i];
    __nv_bfloat162 lo = __floats2bfloat162_rn(v.x, v.y);
    __nv_bfloat162 hi = __floats2bfloat162_rn(v.z, v.w);
    uint2 u;
    u.x = *reinterpret_cast<uint32_t*>(&lo);
    u.y = *reinterpret_cast<uint32_t*>(&hi);
    ((uint2*)dst)[i] = u;
}

// ---------------- kv state: cp.async staging + ones-mma ksum ------------------
// kv[m][d] = sum_s v[s][m]*k[s][d]; ksum via A=ones mma (exact in bf16).
// Tiles token-major (rows = 128 contiguous gmem bytes -> direct cp.async).
#define KTP 72
#define KVTILE (128 * KTP * 2)       // 18432 B per operand tile
#define KVSTG  (2 * KVTILE)          // 36864 B per stage
#define KVSM   (2 * KVSTG)           // 73728 B

__global__ __launch_bounds__(256)
void kv_tc(const __nv_bfloat16* __restrict__ k, const __nv_bfloat16* __restrict__ v,
           float* __restrict__ kvp, float* __restrict__ ksp)
{
    extern __shared__ char smem[];
    const uint32_t smb = smem_u32(smem);

    const int bh = blockIdx.x;
    const int sp = blockIdx.y;
    const int b  = bh / NHEAD, h = bh % NHEAD;
    const int tid  = threadIdx.x;
    const int lane = tid & 31;
    const int wid  = tid >> 5;
    const int mi    = wid & 3;           // m strip 16*mi
    const int dbase = (wid >> 2) * 32;   // d strip

    const int rA = tid >> 3;             // token row 0..31
    const int kg = (tid & 7) * 8;        // dim seg

    const uint32_t sto  = (uint32_t)(rA * KTP + kg) * 2;
    const uint32_t rstp = (uint32_t)(32 * KTP) * 2;

    // ldmatrix.trans lane addresses (token-major tile, fragment = storedᵀ)
    const uint32_t aoff = (uint32_t)(((lane >> 4) << 3) + (lane & 7)) * KTP * 2
                        + (uint32_t)(16 * mi + (((lane >> 3) & 1) << 3)) * 2;
    const uint32_t boff = (uint32_t)((((lane >> 3) & 1) << 3) + (lane & 7)) * KTP * 2
                        + (uint32_t)(dbase + ((lane >> 4) << 3)) * 2;

    const int s_begin = sp * (Sseq / SPLIT);
    const __nv_bfloat16* kp = k + ((size_t)(b * Sseq + s_begin + rA)) * Hdim + h * HDm + kg;
    const __nv_bfloat16* vp = v + ((size_t)(b * Sseq + s_begin + rA)) * Hdim + h * HDm + kg;

    float acc[4][4] = {};
    float aks[4][4] = {};
    const uint32_t ones[4] = {0x3F803F80u, 0x3F803F80u, 0x3F803F80u, 0x3F803F80u};

    const int NT = Sseq / SPLIT / 128;   // 4 tiles of 128 tokens

    // prologue: stage 0
    {
        const uint32_t sb = smb;
        #pragma unroll
        for (int j = 0; j < 4; j++) {
            cp16(sb + sto + j * rstp,          kp + (size_t)(32 * j) * Hdim);
            cp16(sb + KVTILE + sto + j * rstp, vp + (size_t)(32 * j) * Hdim);
        }
        CP_COMMIT();
    }

    for (int tile = 0; tile < NT; tile++) {
        CP_WAIT0();
        __syncthreads();

        if (tile + 1 < NT) {
            const uint32_t sb = smb + ((tile + 1) & 1) * KVSTG;
            const size_t g = (size_t)((tile + 1) * 128) * Hdim;
            #pragma unroll
            for (int j = 0; j < 4; j++) {
                cp16(sb + sto + j * rstp,          kp + g + (size_t)(32 * j) * Hdim);
                cp16(sb + KVTILE + sto + j * rstp, vp + g + (size_t)(32 * j) * Hdim);
            }
            CP_COMMIT();
        }

        const uint32_t ksb = smb + (tile & 1) * KVSTG;
        const uint32_t vsb = ksb + KVTILE;

        #pragma unroll
        for (int st = 0; st < 8; st++) {
            const uint32_t srow = (uint32_t)(st * 16) * KTP * 2;
            uint32_t af[4], bf[4][2];
            ldm_x4t(af[0], af[1], af[2], af[3], vsb + srow + aoff);
            #pragma unroll
            for (int np = 0; np < 2; np++)
                ldm_x4t(bf[np * 2][0], bf[np * 2][1], bf[np * 2 + 1][0], bf[np * 2 + 1][1],
                        ksb + srow + boff + (uint32_t)(np * 16) * 2);
            #pragma unroll
            for (int n = 0; n < 4; n++)
                mma_bf16(acc[n], af, bf[n]);
            if (mi == 0) {
                #pragma unroll
                for (int n = 0; n < 4; n++)
                    mma_bf16(aks[n], ones, bf[n]);
            }
        }
        __syncthreads();
    }

    // write kv partial (no atomics)
    float* kvo = kvp + ((size_t)sp * Bsz * NHEAD + bh) * HDm * HDm;
    #pragma unroll
    for (int n = 0; n < 4; n++) {
        const int d = dbase + 8 * n + 2 * (lane & 3);
        const int m0 = 16 * mi + (lane >> 2);
        *(float2*)(kvo + (m0 + 0) * HDm + d) = make_float2(acc[n][0], acc[n][1]);
        *(float2*)(kvo + (m0 + 8) * HDm + d) = make_float2(acc[n][2], acc[n][3]);
    }

    // ksum partial: ones-mma rows are identical; lanes 0-3 (row 0) write
    if (mi == 0 && (lane >> 2) == 0) {
        float* kso = ksp + ((size_t)sp * Bsz * NHEAD + bh) * HDm;
        #pragma unroll
        for (int n = 0; n < 4; n++) {
            const int d = dbase + 8 * n + 2 * lane;
            *(float2*)(kso + d) = make_float2(aks[n][0], aks[n][1]);
        }
    }
}

// reduce SPLIT partials -> kv, ksum (deterministic)
__global__ void __launch_bounds__(256)
kv_reduce(const float* __restrict__ kvp, const float* __restrict__ ksp,
          float* __restrict__ kv, float* __restrict__ ksum)
{
    const int KVN = Bsz * NHEAD * HDm * HDm;   // 524288
    const int KSN = Bsz * NHEAD * HDm;         // 8192
    const int i = blockIdx.x * 256 + threadIdx.x;
    if (i < KVN) {
        float s = 0.f;
        #pragma unroll
        for (int p = 0; p < SPLIT; p++) s += kvp[(size_t)p * KVN + i];
        kv[i] = s;
    } else if (i < KVN + KSN) {
        const int j = i - KVN;
        float s = 0.f;
        #pragma unroll
        for (int p = 0; p < SPLIT; p++) s += ksp[(size_t)p * KSN + j];
        ksum[j] = s;
    }
}

// ---------------- ctx via tensor cores (frozen) -------------------------------
#define QP 88

__global__ __launch_bounds__(256)
void ctx_tc(const __nv_bfloat16* __restrict__ q, const float* __restrict__ kv,
            const float* __restrict__ ksum, __nv_bfloat16* __restrict__ ctx)
{
    __shared__ __nv_bfloat16 KVb[64 * QP];
    __shared__ __nv_bfloat16 qsm[128 * QP];
    __shared__ float kse[64];
    __shared__ float zr[128];

    const int bh = blockIdx.x;
    const int b  = bh / NHEAD, h = bh % NHEAD;
    const int s0 = blockIdx.y * 128;
    const int tid  = threadIdx.x;
    const int lane = tid & 31;
    const int wid  = tid >> 5;

    const uint32_t kvb = smem_u32(KVb);
    const uint32_t qb_ = smem_u32(qsm);

    const float* kvg = kv + (size_t)bh * HDm * HDm;
    for (int i = tid; i < HDm * HDm; i += 256)
        KVb[(i >> 6) * QP + (i & 63)] = __float2bfloat16(kvg[i]);
    if (tid < 64) kse[tid] = ksum[bh * HDm + tid] + EPS_ATTN;

    {
        const int trow = tid >> 3;
        const int dgrp = tid & 7;
        const size_t gb = ((size_t)(b * Sseq + s0) + trow) * Hdim + h * HDm + dgrp * 8;
        #pragma unroll
        for (int j = 0; j < 4; j++) {
            uint4 r = *(const uint4*)(q + gb + (size_t)(32 * j) * Hdim);
            *(uint4*)((char*)qsm + ((trow + 32 * j) * QP + dgrp * 8) * 2) = r;
        }
    }
    __syncthreads();

    if (tid < 128) {
        float dot = 0.f;
        #pragma unroll 8
        for (int d = 0; d < HDm; d++)
            dot = fmaf(__bfloat162float(qsm[tid * QP + d]), kse[d], dot);
        zr[tid] = 1.f / dot;
    }
    __syncthreads();

    float acc[8][4] = {};
    const int srow = wid * 16;
    #pragma unroll
    for (int kk = 0; kk < 64; kk += 16) {
        uint32_t af[4], bf[8][2];
        ldm_x4(af[0], af[1], af[2], af[3],
               qb_ + (uint32_t)((srow + (lane & 15)) * QP + kk + (lane >> 4) * 8) * 2);
        #pragma unroll
        for (int np = 0; np < 4; np++)
            ldm_x4(bf[np * 2][0], bf[np * 2][1], bf[np * 2 + 1][0], bf[np * 2 + 1][1],
                   kvb + (uint32_t)((np * 16 + ((lane >> 4) << 3) + (lane & 7)) * QP
                                    + kk + ((lane >> 3) & 1) * 8) * 2);
        #pragma unroll
        for (int n = 0; n < 8; n++)
            mma_bf16(acc[n], af, bf[n]);
    }

    const int r = lane >> 2;
    const int c = 2 * (lane & 3);
    #pragma unroll
    for (int half = 0; half < 2; half++) {
        const int tl = srow + r + half * 8;
        const float z = zr[tl];
        const size_t base = ((size_t)(b * Sseq + s0 + tl)) * Hdim + h * HDm;
        #pragma unroll
        for (int n = 0; n < 8; n++) {
            const int m = 8 * n + c;
            *(__nv_bfloat162*)(ctx + base + m) =
                __floats2bfloat162_rn(acc[n][half * 2 + 0] * z, acc[n][half * 2 + 1] * z);
        }
    }
}

// ---------------- LayerNorm over rows of 1024
__global__ __launch_bounds__(256)
void ln_kernel(const float* __restrict__ hs, const float* __restrict__ gamma,
               const float* __restrict__ beta, float* __restrict__ out)
{
    const int row = blockIdx.x;
    const int tid = threadIdx.x;
    const float4 v = ((const float4*)(hs + (size_t)row * Hdim))[tid];

    float s  = v.x + v.y + v.z + v.w;
    float sq = v.x * v.x + v.y * v.y + v.z * v.z + v.w * v.w;
    #pragma unroll
    for (int o = 16; o > 0; o >>= 1) {
        s  += __shfl_xor_sync(0xFFFFFFFFu, s, o);
        sq += __shfl_xor_sync(0xFFFFFFFFu, sq, o);
    }
    __shared__ float rs[8], rq[8];
    const int wid = tid >> 5, lane = tid & 31;
    if (lane == 0) { rs[wid] = s; rq[wid] = sq; }
    __syncthreads();
    float sum = 0.f, sumq = 0.f;
    #pragma unroll
    for (int i = 0; i < 8; i++) { sum += rs[i]; sumq += rq[i]; }

    const float mu   = sum * (1.f / Hdim);
    const float var  = sumq * (1.f / Hdim) - mu * mu;
    const float rstd = rsqrtf(var + EPS_LN);

    const float4 g4 = ((const float4*)gamma)[tid];
    const float4 b4 = ((const float4*)beta)[tid];
    float4 o;
    o.x = (v.x - mu) * rstd * g4.x + b4.x;
    o.y = (v.y - mu) * rstd * g4.y + b4.y;
    o.z = (v.z - mu) * rstd * g4.z + b4.z;
    o.w = (v.w - mu) * rstd * g4.w + b4.w;
    ((float4*)(out + (size_t)row * Hdim))[tid] = o;
}

// ---------------- launch ----------------------------------------------------
extern "C" void kernel_launch(void* const* d_in, const int* in_sizes, int n_in,
                              void* d_out, int out_size)
{
    const float* x     = (const float*)d_in[0];
    const float* Wq    = (const float*)d_in[2];
    const float* bq    = (const float*)d_in[3];
    const float* Wk    = (const float*)d_in[4];
    const float* bk    = (const float*)d_in[5];
    const float* Wv    = (const float*)d_in[6];
    const float* bv    = (const float*)d_in[7];
    const float* Wd    = (const float*)d_in[8];
    const float* bd    = (const float*)d_in[9];
    const float* gamma = (const float*)d_in[10];
    const float* beta  = (const float*)d_in[11];
    float* out = (float*)d_out;

    float *hs, *kv, *ksum, *kvp, *ksp;
    __nv_bfloat16 *qb, *kb, *vb, *xb, *cb, *wqkv, *wdb;
    cudaGetSymbolAddress((void**)&hs,   g_hs);
    cudaGetSymbolAddress((void**)&qb,   g_qb);
    cudaGetSymbolAddress((void**)&kb,   g_kb);
    cudaGetSymbolAddress((void**)&vb,   g_vb);
    cudaGetSymbolAddress((void**)&kv,   g_kv);
    cudaGetSymbolAddress((void**)&ksum, g_ksum);
    cudaGetSymbolAddress((void**)&kvp,  g_kvp);
    cudaGetSymbolAddress((void**)&ksp,  g_ksp);
    cudaGetSymbolAddress((void**)&xb,   g_xb);
    cudaGetSymbolAddress((void**)&cb,   g_cb);
    cudaGetSymbolAddress((void**)&wqkv, g_wqkv);
    cudaGetSymbolAddress((void**)&wdb,  g_wd);

    cudaFuncSetAttribute(gemm_bf16, cudaFuncAttributeMaxDynamicSharedMemorySize, GSM_TOT);
    cudaFuncSetAttribute(kv_tc,     cudaFuncAttributeMaxDynamicSharedMemorySize, KVSM);

    const int xn4 = (int)((size_t)BSROWS * Hdim / 4);
    const int wn4 = Hdim * Hdim / 4;

    // idx0-2: conversions (gemm lands at idx3 for the profiler)
    conv_bf16<<<xn4 / 256, 256>>>(x, xb, xn4);
    conv_w3<<<3 * (wn4 / 256), 256>>>(Wq, Wk, Wv, wqkv);
    conv_bf16<<<wn4 / 256, 256>>>(Wd, wdb, wn4);

    // idx3: fused QKV GEMM (+ elu+1 on q,k), bf16 outputs
    gemm_bf16<<<dim3(3 * Hdim / 128, BSROWS / 128), 256, GSM_TOT>>>(
        xb, wqkv, bq, bk, bv, nullptr, nullptr, qb, kb, vb, Hdim, 1);

    // idx4: kv state + ksum (split-S x8, cp.async, ones-mma ksum)
    kv_tc<<<dim3(Bsz * NHEAD, SPLIT), 256, KVSM>>>(kb, vb, kvp, ksp);

    // idx5: reduce partials
    {
        const int n = Bsz * NHEAD * HDm * HDm + Bsz * NHEAD * HDm;
        kv_reduce<<<(n + 255) / 256, 256>>>(kvp, ksp, kv, ksum);
    }

    // idx6: ctx
    ctx_tc<<<dim3(Bsz * NHEAD, Sseq / 128), 256>>>(qb, kv, ksum, cb);

    // idx7: output projection + bias + residual -> hs (f32)
    gemm_bf16<<<dim3(Hdim / 128, BSROWS / 128), 256, GSM_TOT>>>(
        cb, wdb, bd, bd, bd, x, hs, nullptr, nullptr, nullptr, Hdim, 0);

    // idx8: LayerNorm
    ln_kernel<<<BSROWS, 256>>>(hs, gamma, beta, out);
}